// round 12
// baseline (speedup 1.0000x reference)
#include <cuda_runtime.h>
#include <cuda_fp16.h>
#include <cstdint>

// Problem constants
#define Bn   2
#define Tn   2048
#define Cn   2048
#define NQn  16
#define NKVn 4
#define Hn   128
#define BTn  (Bn*Tn)        // 4096
#define NQKV 3072           // 2048 q + 512 k + 512 v
#define SCALE 0.08838834764831845f  // 1/sqrt(128)

// ---------------- scratch (device globals) ------------------------------------
__device__ __half g_qkvh[BTn * NQKV];            // fused qkv proj fp16 (v region used)
__device__ __half g_xh[BTn * Cn];                // x fp16 [M][K]
__device__ __half g_wqkvh[Cn * NQKV];            // [Wq | Wk | Wv] fp16 [K][3072]
__device__ __half g_woh[(NQn*Hn) * Cn];          // Wo fp16 [K][N]
__device__ __half g_ctxh[BTn * NQn * Hn];        // attention out fp16
__device__ __half g_qh[Bn * NQn * Tn * Hn];      // q fp16 [b][h][t][d] (pre-scaled)
__device__ __half g_kh[Bn * NKVn * Tn * Hn];     // k fp16 [b][kvh][t][d]

// ---------------- helpers ------------------------------------------------------
__device__ __forceinline__ uint32_t smem_u32(const void* p) {
    uint32_t a;
    asm("{ .reg .u64 t; cvta.to.shared.u64 t, %1; cvt.u32.u64 %0, t; }" : "=r"(a) : "l"(p));
    return a;
}
__device__ __forceinline__ void ldmatrix_x4(uint32_t& r0, uint32_t& r1,
                                            uint32_t& r2, uint32_t& r3, uint32_t addr) {
    asm volatile("ldmatrix.sync.aligned.m8n8.x4.shared.b16 {%0,%1,%2,%3}, [%4];"
                 : "=r"(r0), "=r"(r1), "=r"(r2), "=r"(r3) : "r"(addr));
}
__device__ __forceinline__ void ldmatrix_x4_trans(uint32_t& r0, uint32_t& r1,
                                                  uint32_t& r2, uint32_t& r3, uint32_t addr) {
    asm volatile("ldmatrix.sync.aligned.m8n8.x4.trans.shared.b16 {%0,%1,%2,%3}, [%4];"
                 : "=r"(r0), "=r"(r1), "=r"(r2), "=r"(r3) : "r"(addr));
}
__device__ __forceinline__ void mma16816(float* d, const uint32_t* a, const uint32_t* b) {
    asm volatile(
        "mma.sync.aligned.m16n8k16.row.col.f32.f16.f16.f32 "
        "{%0,%1,%2,%3}, {%4,%5,%6,%7}, {%8,%9}, {%0,%1,%2,%3};"
        : "+f"(d[0]), "+f"(d[1]), "+f"(d[2]), "+f"(d[3])
        : "r"(a[0]), "r"(a[1]), "r"(a[2]), "r"(a[3]), "r"(b[0]), "r"(b[1]));
}
__device__ __forceinline__ void cp16(uint32_t dst, const void* src) {
    asm volatile("cp.async.cg.shared.global [%0], [%1], 16;"
                 :: "r"(dst), "l"(__cvta_generic_to_global(src)));
}
#define CP_COMMIT() asm volatile("cp.async.commit_group;")

// ---------------- fp32 -> fp16 elementwise ------------------------------------
__global__ void f32_to_f16_kernel(const float* __restrict__ in, __half* __restrict__ out, int n4) {
    int i = blockIdx.x * blockDim.x + threadIdx.x;
    if (i < n4) {
        float4 v = ((const float4*)in)[i];
        ((__half2*)out)[2*i]   = __floats2half2_rn(v.x, v.y);
        ((__half2*)out)[2*i+1] = __floats2half2_rn(v.z, v.w);
    }
}

// ---------------- all weight conversions in ONE launch -------------------------
// regions (in half2 units / 256-thread blocks):
//   [0,8192)      Wq  -> wqkvh stride 3072 off 0      (2048x2048)
//   [8192,10240)  Wk  -> wqkvh stride 3072 off 2048   (2048x512)
//   [10240,12288) Wv  -> wqkvh stride 3072 off 2560   (2048x512)
//   [12288,20480) Wo  -> woh   stride 2048 off 0      (2048x2048)
__global__ void wconv_all(const float* __restrict__ Wq, const float* __restrict__ Wk,
                          const float* __restrict__ Wv, const float* __restrict__ Wo,
                          __half* __restrict__ wqkvh, __half* __restrict__ woh) {
    int bid = blockIdx.x, tid = threadIdx.x;
    const float* src; __half* dst; int N, stride, off, i;
    if (bid < 8192)       { src = Wq; dst = wqkvh; N = 2048; stride = NQKV; off = 0;
                            i = bid * 256 + tid; }
    else if (bid < 10240) { src = Wk; dst = wqkvh; N = 512;  stride = NQKV; off = 2048;
                            i = (bid - 8192) * 256 + tid; }
    else if (bid < 12288) { src = Wv; dst = wqkvh; N = 512;  stride = NQKV; off = 2560;
                            i = (bid - 10240) * 256 + tid; }
    else                  { src = Wo; dst = woh;   N = 2048; stride = 2048; off = 0;
                            i = (bid - 12288) * 256 + tid; }
    float2 v = ((const float2*)src)[i];
    int row = i / (N >> 1), c2 = i % (N >> 1);
    *(__half2*)&dst[(size_t)row * stride + off + 2 * c2] = __floats2half2_rn(v.x, v.y);
}

// ---------------- HMMA GEMM 128x256, 3-stage cp.async, B natural [K][N] -------
// FUSE=true (QKV): N-tiles 0-7 = q (norm+rope+SCALE -> qh), 8-9 = k (-> kh),
// 10-11 = v (plain fp16 -> qkvh). FUSE=false: plain OutT epilogue.
#define GP 40
#define BP 264
#define G_AH (128*GP)
#define G_BH (32*BP)
#define G_STAGE_H (G_AH + G_BH)
#define GSTG 3
#define G_SMEM_B (GSTG * G_STAGE_H * 2)   // 81408 bytes (>= Ctile 128*258*2 = 66048)
#define SP 258                            // Ctile smem pitch (halfs); words/row = 129 (odd)

template<typename OutT, bool FUSE>
__global__ void __launch_bounds__(256) hgemm_pipe(const __half* __restrict__ A,
                                                  const __half* __restrict__ B,
                                                  OutT* __restrict__ C,
                                                  int M, int N, int K, int ldB,
                                                  __half* __restrict__ qh,
                                                  __half* __restrict__ kh,
                                                  const float* __restrict__ qnw,
                                                  const float* __restrict__ knw,
                                                  const float* __restrict__ cosb,
                                                  const float* __restrict__ sinb) {
    extern __shared__ __half hsm[];
    uint32_t smb = smem_u32(hsm);
    int tid = threadIdx.x;
    int lane = tid & 31, wid = tid >> 5;
    int wm = wid >> 2, wn = wid & 3;
    int m0 = blockIdx.y << 7, n0 = blockIdx.x << 8;

    const int NC = K >> 5;

    auto issue = [&](int c) {
        int s = c % GSTG;
        uint32_t base = smb + s * (G_STAGE_H * 2);
        #pragma unroll
        for (int i = 0; i < 2; i++) {
            int f = tid + i * 256; int r = f >> 2, cc = (f & 3) * 8;
            cp16(base + (r * GP + cc) * 2, A + (size_t)(m0 + r) * K + c * 32 + cc);
        }
        #pragma unroll
        for (int i = 0; i < 4; i++) {
            int f = tid + i * 256; int kr = f >> 5, nc = (f & 31) * 8;
            cp16(base + (G_AH + kr * BP + nc) * 2,
                 B + (size_t)(c * 32 + kr) * ldB + n0 + nc);
        }
        CP_COMMIT();
    };

    issue(0); issue(1);

    float acc[4][8][4];
    #pragma unroll
    for (int i = 0; i < 4; i++)
        #pragma unroll
        for (int j = 0; j < 8; j++)
            #pragma unroll
            for (int k = 0; k < 4; k++) acc[i][j][k] = 0.f;

    int lrow = lane & 15, lhalf = lane >> 4;

    for (int c = 0; c < NC; c++) {
        asm volatile("cp.async.wait_group 1;");
        __syncthreads();
        if (c + 2 < NC) issue(c + 2);

        uint32_t sbase = smb + (c % GSTG) * (G_STAGE_H * 2);
        #pragma unroll
        for (int ks = 0; ks < 2; ks++) {
            uint32_t af[4][4];
            uint32_t bf[8][2];
            #pragma unroll
            for (int mt = 0; mt < 4; mt++) {
                uint32_t ad = sbase + ((wm*64 + mt*16 + lrow) * GP + ks*16 + lhalf*8) * 2;
                ldmatrix_x4(af[mt][0], af[mt][1], af[mt][2], af[mt][3], ad);
            }
            #pragma unroll
            for (int np = 0; np < 4; np++) {
                uint32_t bd = sbase + (G_AH + (ks*16 + lrow) * BP + wn*64 + np*16 + lhalf*8) * 2;
                uint32_t q0, q1, q2, q3;
                ldmatrix_x4_trans(q0, q1, q2, q3, bd);
                bf[np*2+0][0] = q0; bf[np*2+0][1] = q1;
                bf[np*2+1][0] = q2; bf[np*2+1][1] = q3;
            }
            #pragma unroll
            for (int mt = 0; mt < 4; mt++)
                #pragma unroll
                for (int nt = 0; nt < 8; nt++)
                    mma16816(acc[mt][nt], af[mt], bf[nt]);
        }
    }

    int er = lane >> 2, ec = (lane & 3) * 2;

    bool fuse_tile = FUSE && ((int)blockIdx.x < 10);
    if (!fuse_tile) {
        // plain epilogue (v tiles when FUSE, everything when !FUSE)
        #pragma unroll
        for (int mt = 0; mt < 4; mt++) {
            int row = m0 + wm*64 + mt*16 + er;
            OutT* Cr0 = C + (size_t)row * N + n0 + wn*64;
            OutT* Cr1 = Cr0 + 8 * N;
            #pragma unroll
            for (int nt = 0; nt < 8; nt++) {
                if constexpr (sizeof(OutT) == 2) {
                    *(__half2*)&Cr0[nt*8 + ec] = __floats2half2_rn(acc[mt][nt][0], acc[mt][nt][1]);
                    *(__half2*)&Cr1[nt*8 + ec] = __floats2half2_rn(acc[mt][nt][2], acc[mt][nt][3]);
                } else {
                    *(float2*)&Cr0[nt*8 + ec] = make_float2(acc[mt][nt][0], acc[mt][nt][1]);
                    *(float2*)&Cr1[nt*8 + ec] = make_float2(acc[mt][nt][2], acc[mt][nt][3]);
                }
            }
        }
        return;
    }

    // ---- fused norm + rope epilogue (q/k tiles) ----
    __syncthreads();   // all warps done with pipeline smem
    // write fragments to smem Ctile [128][SP]
    #pragma unroll
    for (int mt = 0; mt < 4; mt++) {
        int lr0 = wm*64 + mt*16 + er;
        #pragma unroll
        for (int nt = 0; nt < 8; nt++) {
            int cl = wn*64 + nt*8 + ec;
            *(__half2*)&hsm[lr0 * SP + cl]       = __floats2half2_rn(acc[mt][nt][0], acc[mt][nt][1]);
            *(__half2*)&hsm[(lr0 + 8) * SP + cl] = __floats2half2_rn(acc[mt][nt][2], acc[mt][nt][3]);
        }
    }
    __syncthreads();

    // norm pass: thread = (row lr 0..127, head-half hh 0..1)
    {
        int lr = tid & 127, hh = tid >> 7;
        int grow = m0 + lr;
        int t = grow & (Tn - 1), b = grow >> 11;
        bool isQ = ((int)blockIdx.x < 8);
        int h = isQ ? ((int)blockIdx.x * 2 + hh) : (((int)blockIdx.x - 8) * 2 + hh);
        const float* wv = isQ ? qnw : knw;

        const __half* crow = &hsm[lr * SP + hh * 128];
        __half2 xs[64];
        float ss = 0.f;
        #pragma unroll
        for (int j = 0; j < 64; j++) {
            xs[j] = *(const __half2*)&crow[2 * j];
            float2 f = __half22float2(xs[j]);
            ss += f.x * f.x + f.y * f.y;
        }
        float inv = rsqrtf(ss * (1.0f / 128.0f) + 1e-6f);
        if (isQ) inv *= SCALE;     // rope is linear; fold attention scale into q

        const float* cr = cosb + (size_t)t * Hn;
        const float* sr = sinb + (size_t)t * Hn;
        __half* orow = (isQ ? qh : kh) +
            ((size_t)((b * (isQ ? NQn : NKVn) + h) * Tn + t)) * Hn;

        #pragma unroll
        for (int blk = 0; blk < 8; blk++) {
            __half2 yo[8];
            #pragma unroll
            for (int p = 0; p < 8; p++) {
                int d0 = blk * 16 + p * 2;          // even d
                float2 xv = __half22float2(xs[d0 >> 1]);
                float2 pv = __half22float2(xs[(d0 < 64) ? (32 + (d0 >> 1)) : ((d0 >> 1) - 32)]);
                float2 w2  = *(const float2*)&wv[d0];
                float2 pw2 = *(const float2*)&wv[(d0 < 64) ? (d0 + 64) : (d0 - 64)];
                float2 c2 = *(const float2*)&cr[d0];
                float2 s2 = *(const float2*)&sr[d0];
                float xn0 = xv.x * inv * w2.x, xn1 = xv.y * inv * w2.y;
                float pn0 = pv.x * inv * pw2.x, pn1 = pv.y * inv * pw2.y;
                float y0, y1;
                if (d0 < 64) { y0 = xn0 * c2.x - pn0 * s2.x; y1 = xn1 * c2.y - pn1 * s2.y; }
                else         { y0 = xn0 * c2.x + pn0 * s2.x; y1 = xn1 * c2.y + pn1 * s2.y; }
                yo[p] = __floats2half2_rn(y0, y1);
            }
            uint4 o4;
            o4.x = *(uint32_t*)&yo[0]; o4.y = *(uint32_t*)&yo[1];
            o4.z = *(uint32_t*)&yo[2]; o4.w = *(uint32_t*)&yo[3];
            *(uint4*)&orow[blk * 16] = o4;
            uint4 o5;
            o5.x = *(uint32_t*)&yo[4]; o5.y = *(uint32_t*)&yo[5];
            o5.z = *(uint32_t*)&yo[6]; o5.w = *(uint32_t*)&yo[7];
            *(uint4*)&orow[blk * 16 + 8] = o5;
        }
    }
}

// ---------------- HMMA flash attention (causal, GQA) ---------------------------
// 64 q-rows per CTA, 128 threads, kv tiles of 64, cp.async double buffer,
// descending-q0 launch order. q pre-scaled by 1/sqrt(H).
#define AKP 136
#define A_KB (64 * AKP)
#define A_STAGE_H (2 * A_KB)
#define A_SMEM_B (2 * A_STAGE_H * 2)  // 69632 bytes
__global__ void __launch_bounds__(128) attn_mma(const __half* __restrict__ qh,
                                                const __half* __restrict__ kh,
                                                const __half* __restrict__ qkvh,
                                                __half* __restrict__ ctxh) {
    extern __shared__ __half asm_[];
    uint32_t smb = smem_u32(asm_);

    int tid = threadIdx.x, lane = tid & 31, w = tid >> 5;
    int q0 = (gridDim.x - 1 - blockIdx.x) << 6;
    int h = blockIdx.y, b = blockIdx.z;
    int kvh = h >> 2;

    const __half* qb = qh + ((size_t)(b * NQn + h) * Tn + q0) * Hn;
    const __half* kb = kh + (size_t)(b * NKVn + kvh) * Tn * Hn;
    const __half* vb = qkvh + (size_t)b * Tn * NQKV + 2560 + kvh * Hn;

    #pragma unroll
    for (int i = 0; i < 8; i++) {
        int f = tid + i * 128; int r = f >> 4, c8 = (f & 15) << 3;
        *(uint4*)&asm_[r * AKP + c8] = *(const uint4*)(qb + (size_t)r * Hn + c8);
    }
    __syncthreads();
    int lrow = lane & 15, lhalf = lane >> 4;
    uint32_t qf[8][4];
    #pragma unroll
    for (int ks = 0; ks < 8; ks++) {
        uint32_t ad = smb + ((w * 16 + lrow) * AKP + ks * 16 + lhalf * 8) * 2;
        ldmatrix_x4(qf[ks][0], qf[ks][1], qf[ks][2], qf[ks][3], ad);
    }
    __syncthreads();

    auto issue_kv = [&](int jt) {
        uint32_t base = smb + (jt & 1) * (A_STAGE_H * 2);
        int j0 = jt << 6;
        #pragma unroll
        for (int i = 0; i < 8; i++) {
            int f = tid + i * 128; int r = f >> 4, c8 = (f & 15) << 3;
            cp16(base + (r * AKP + c8) * 2, kb + (size_t)(j0 + r) * Hn + c8);
        }
        #pragma unroll
        for (int i = 0; i < 8; i++) {
            int f = tid + i * 128; int r = f >> 4, c8 = (f & 15) << 3;
            cp16(base + (A_KB + r * AKP + c8) * 2, vb + (size_t)(j0 + r) * NQKV + c8);
        }
        CP_COMMIT();
    };

    const int NT = (q0 >> 6) + 1;
    issue_kv(0);

    float oacc[16][4];
    #pragma unroll
    for (int i = 0; i < 16; i++) { oacc[i][0]=0.f; oacc[i][1]=0.f; oacc[i][2]=0.f; oacc[i][3]=0.f; }
    float m0 = -1e30f, m1 = -1e30f, l0 = 0.f, l1 = 0.f;
    int ec = (lane & 3) * 2;
    int r0 = q0 + w * 16 + (lane >> 2);
    int r1 = r0 + 8;

    for (int jt = 0; jt < NT; jt++) {
        int j0 = jt << 6;
        if (jt + 1 < NT) {
            issue_kv(jt + 1);
            asm volatile("cp.async.wait_group 1;");
        } else {
            asm volatile("cp.async.wait_group 0;");
        }
        __syncthreads();
        uint32_t sbase = smb + (jt & 1) * (A_STAGE_H * 2);

        float sacc[8][4];
        #pragma unroll
        for (int i = 0; i < 8; i++) { sacc[i][0]=0.f; sacc[i][1]=0.f; sacc[i][2]=0.f; sacc[i][3]=0.f; }
        #pragma unroll
        for (int ks = 0; ks < 8; ks++) {
            #pragma unroll
            for (int np = 0; np < 4; np++) {
                uint32_t ad = sbase + ((np * 16 + lrow) * AKP + ks * 16 + lhalf * 8) * 2;
                uint32_t t0, t1, t2, t3;
                ldmatrix_x4(t0, t1, t2, t3, ad);
                uint32_t b0[2] = {t0, t2}, b1[2] = {t1, t3};
                mma16816(sacc[np * 2],     qf[ks], b0);
                mma16816(sacc[np * 2 + 1], qf[ks], b1);
            }
        }

        // causal mask (q already scaled)
        #pragma unroll
        for (int nt = 0; nt < 8; nt++) {
            int c = j0 + nt * 8 + ec;
            if (c     > r0) sacc[nt][0] = -1e30f;
            if (c + 1 > r0) sacc[nt][1] = -1e30f;
            if (c     > r1) sacc[nt][2] = -1e30f;
            if (c + 1 > r1) sacc[nt][3] = -1e30f;
        }

        float tm0 = -1e30f, tm1 = -1e30f;
        #pragma unroll
        for (int nt = 0; nt < 8; nt++) {
            tm0 = fmaxf(tm0, fmaxf(sacc[nt][0], sacc[nt][1]));
            tm1 = fmaxf(tm1, fmaxf(sacc[nt][2], sacc[nt][3]));
        }
        tm0 = fmaxf(tm0, __shfl_xor_sync(0xffffffffu, tm0, 1));
        tm0 = fmaxf(tm0, __shfl_xor_sync(0xffffffffu, tm0, 2));
        tm1 = fmaxf(tm1, __shfl_xor_sync(0xffffffffu, tm1, 1));
        tm1 = fmaxf(tm1, __shfl_xor_sync(0xffffffffu, tm1, 2));
        float mn0 = fmaxf(m0, tm0), mn1 = fmaxf(m1, tm1);
        float al0 = __expf(m0 - mn0), al1 = __expf(m1 - mn1);
        m0 = mn0; m1 = mn1;

        float rs0 = 0.f, rs1 = 0.f;
        uint32_t pf[4][4];
        #pragma unroll
        for (int nt = 0; nt < 8; nt++) {
            float p0 = __expf(sacc[nt][0] - mn0);
            float p1 = __expf(sacc[nt][1] - mn0);
            float p2 = __expf(sacc[nt][2] - mn1);
            float p3 = __expf(sacc[nt][3] - mn1);
            rs0 += p0 + p1; rs1 += p2 + p3;
            __half2 v01 = __floats2half2_rn(p0, p1);
            __half2 v23 = __floats2half2_rn(p2, p3);
            int kt = nt >> 1;
            if ((nt & 1) == 0) {
                pf[kt][0] = *(uint32_t*)&v01;
                pf[kt][1] = *(uint32_t*)&v23;
            } else {
                pf[kt][2] = *(uint32_t*)&v01;
                pf[kt][3] = *(uint32_t*)&v23;
            }
        }
        rs0 += __shfl_xor_sync(0xffffffffu, rs0, 1);
        rs0 += __shfl_xor_sync(0xffffffffu, rs0, 2);
        rs1 += __shfl_xor_sync(0xffffffffu, rs1, 1);
        rs1 += __shfl_xor_sync(0xffffffffu, rs1, 2);
        l0 = l0 * al0 + rs0;
        l1 = l1 * al1 + rs1;

        #pragma unroll
        for (int dt = 0; dt < 16; dt++) {
            oacc[dt][0] *= al0; oacc[dt][1] *= al0;
            oacc[dt][2] *= al1; oacc[dt][3] *= al1;
        }

        #pragma unroll
        for (int kt = 0; kt < 4; kt++) {
            #pragma unroll
            for (int np = 0; np < 8; np++) {
                uint32_t ad = sbase + (A_KB + (kt * 16 + lrow) * AKP + np * 16 + lhalf * 8) * 2;
                uint32_t t0, t1, t2, t3;
                ldmatrix_x4_trans(t0, t1, t2, t3, ad);
                uint32_t b0[2] = {t0, t1}, b1[2] = {t2, t3};
                mma16816(oacc[np * 2],     pf[kt], b0);
                mma16816(oacc[np * 2 + 1], pf[kt], b1);
            }
        }
        __syncthreads();
    }

    float inv0 = 1.0f / l0, inv1 = 1.0f / l1;
    __half* o0 = ctxh + (size_t)(b * Tn + r0) * (NQn * Hn) + h * Hn;
    __half* o1 = ctxh + (size_t)(b * Tn + r1) * (NQn * Hn) + h * Hn;
    #pragma unroll
    for (int dt = 0; dt < 16; dt++) {
        __half2 w0 = __floats2half2_rn(oacc[dt][0] * inv0, oacc[dt][1] * inv0);
        __half2 w1 = __floats2half2_rn(oacc[dt][2] * inv1, oacc[dt][3] * inv1);
        *(__half2*)&o0[dt * 8 + ec] = w0;
        *(__half2*)&o1[dt * 8 + ec] = w1;
    }
}

// ---------------- launch ------------------------------------------------------
extern "C" void kernel_launch(void* const* d_in, const int* in_sizes, int n_in,
                              void* d_out, int out_size) {
    (void)in_sizes; (void)n_in; (void)out_size;
    const float* x   = (const float*)d_in[0];
    const float* Wq  = (const float*)d_in[1];
    const float* Wk  = (const float*)d_in[2];
    const float* Wv  = (const float*)d_in[3];
    const float* Wo  = (const float*)d_in[4];
    const float* qnw = (const float*)d_in[5];
    const float* knw = (const float*)d_in[6];
    const float* cosb = (const float*)d_in[7];
    const float* sinb = (const float*)d_in[8];
    float* out = (float*)d_out;

    __half *qkvh, *xh, *wqkvh, *woh, *ctxh, *qh, *kh;
    cudaGetSymbolAddress((void**)&qkvh,  g_qkvh);
    cudaGetSymbolAddress((void**)&xh,    g_xh);
    cudaGetSymbolAddress((void**)&wqkvh, g_wqkvh);
    cudaGetSymbolAddress((void**)&woh,   g_woh);
    cudaGetSymbolAddress((void**)&ctxh,  g_ctxh);
    cudaGetSymbolAddress((void**)&qh,    g_qh);
    cudaGetSymbolAddress((void**)&kh,    g_kh);

    cudaFuncSetAttribute((const void*)hgemm_pipe<__half, true>,
                         cudaFuncAttributeMaxDynamicSharedMemorySize, G_SMEM_B);
    cudaFuncSetAttribute((const void*)hgemm_pipe<float, false>,
                         cudaFuncAttributeMaxDynamicSharedMemorySize, G_SMEM_B);
    cudaFuncSetAttribute((const void*)attn_mma,
                         cudaFuncAttributeMaxDynamicSharedMemorySize, A_SMEM_B);

    // 0) conversions (1 launch for all weights, 1 for x)
    wconv_all<<<20480, 256>>>(Wq, Wk, Wv, Wo, wqkvh, woh);
    f32_to_f16_kernel<<<(BTn * Cn / 4 + 255) / 256, 256>>>(x, xh, BTn * Cn / 4);

    // 1) fused QKV projection + RMSNorm + RoPE (+SCALE on q)
    hgemm_pipe<__half, true><<<dim3(NQKV/256, BTn/128), 256, G_SMEM_B>>>(
        xh, wqkvh, qkvh, BTn, NQKV, Cn, NQKV, qh, kh, qnw, knw, cosb, sinb);

    // 2) causal GQA flash attention (V read in-place from qkvh)
    attn_mma<<<dim3(Tn / 64, NQn, Bn), 128, A_SMEM_B>>>(qh, kh, qkvh, ctxh);

    // 3) output projection -> f32
    hgemm_pipe<float, false><<<dim3(Cn/256, BTn/128), 256, G_SMEM_B>>>(
        ctxh, woh, out, BTn, Cn, NQn*Hn, Cn, nullptr, nullptr, nullptr, nullptr, nullptr, nullptr);
}

// round 13
// speedup vs baseline: 1.0884x; 1.0884x over previous
#include <cuda_runtime.h>
#include <cuda_fp16.h>
#include <cstdint>

// Problem constants
#define Bn   2
#define Tn   2048
#define Cn   2048
#define NQn  16
#define NKVn 4
#define Hn   128
#define BTn  (Bn*Tn)        // 4096
#define NQKV 3072           // 2048 q + 512 k + 512 v
#define SCALE 0.08838834764831845f  // 1/sqrt(128)

// ---------------- scratch (device globals) ------------------------------------
__device__ __half g_qkvh[BTn * NQKV];            // fused qkv proj fp16 [bt][3072]
__device__ __half g_xh[BTn * Cn];                // x fp16 [M][K]
__device__ __half g_wqkvh[Cn * NQKV];            // [Wq | Wk | Wv] fp16 [K][3072]
__device__ __half g_woh[(NQn*Hn) * Cn];          // Wo fp16 [K][N]
__device__ __half g_ctxh[BTn * NQn * Hn];        // attention out fp16
__device__ __half g_qh[Bn * NQn * Tn * Hn];      // q fp16 [b][h][t][d]
__device__ __half g_kh[Bn * NKVn * Tn * Hn];     // k fp16 [b][kvh][t][d]

// ---------------- helpers ------------------------------------------------------
__device__ __forceinline__ uint32_t smem_u32(const void* p) {
    uint32_t a;
    asm("{ .reg .u64 t; cvta.to.shared.u64 t, %1; cvt.u32.u64 %0, t; }" : "=r"(a) : "l"(p));
    return a;
}
__device__ __forceinline__ void ldmatrix_x4(uint32_t& r0, uint32_t& r1,
                                            uint32_t& r2, uint32_t& r3, uint32_t addr) {
    asm volatile("ldmatrix.sync.aligned.m8n8.x4.shared.b16 {%0,%1,%2,%3}, [%4];"
                 : "=r"(r0), "=r"(r1), "=r"(r2), "=r"(r3) : "r"(addr));
}
__device__ __forceinline__ void ldmatrix_x4_trans(uint32_t& r0, uint32_t& r1,
                                                  uint32_t& r2, uint32_t& r3, uint32_t addr) {
    asm volatile("ldmatrix.sync.aligned.m8n8.x4.trans.shared.b16 {%0,%1,%2,%3}, [%4];"
                 : "=r"(r0), "=r"(r1), "=r"(r2), "=r"(r3) : "r"(addr));
}
__device__ __forceinline__ void mma16816(float* d, const uint32_t* a, const uint32_t* b) {
    asm volatile(
        "mma.sync.aligned.m16n8k16.row.col.f32.f16.f16.f32 "
        "{%0,%1,%2,%3}, {%4,%5,%6,%7}, {%8,%9}, {%0,%1,%2,%3};"
        : "+f"(d[0]), "+f"(d[1]), "+f"(d[2]), "+f"(d[3])
        : "r"(a[0]), "r"(a[1]), "r"(a[2]), "r"(a[3]), "r"(b[0]), "r"(b[1]));
}
__device__ __forceinline__ void cp16(uint32_t dst, const void* src) {
    asm volatile("cp.async.cg.shared.global [%0], [%1], 16;"
                 :: "r"(dst), "l"(__cvta_generic_to_global(src)));
}
#define CP_COMMIT() asm volatile("cp.async.commit_group;")

// ---------------- fp32 -> fp16 elementwise ------------------------------------
__global__ void f32_to_f16_kernel(const float* __restrict__ in, __half* __restrict__ out, int n4) {
    int i = blockIdx.x * blockDim.x + threadIdx.x;
    if (i < n4) {
        float4 v = ((const float4*)in)[i];
        ((__half2*)out)[2*i]   = __floats2half2_rn(v.x, v.y);
        ((__half2*)out)[2*i+1] = __floats2half2_rn(v.z, v.w);
    }
}

// ---------------- all weight conversions in ONE launch -------------------------
__global__ void wconv_all(const float* __restrict__ Wq, const float* __restrict__ Wk,
                          const float* __restrict__ Wv, const float* __restrict__ Wo,
                          __half* __restrict__ wqkvh, __half* __restrict__ woh) {
    int bid = blockIdx.x, tid = threadIdx.x;
    const float* src; __half* dst; int N, stride, off, i;
    if (bid < 8192)       { src = Wq; dst = wqkvh; N = 2048; stride = NQKV; off = 0;
                            i = bid * 256 + tid; }
    else if (bid < 10240) { src = Wk; dst = wqkvh; N = 512;  stride = NQKV; off = 2048;
                            i = (bid - 8192) * 256 + tid; }
    else if (bid < 12288) { src = Wv; dst = wqkvh; N = 512;  stride = NQKV; off = 2560;
                            i = (bid - 10240) * 256 + tid; }
    else                  { src = Wo; dst = woh;   N = 2048; stride = 2048; off = 0;
                            i = (bid - 12288) * 256 + tid; }
    float2 v = ((const float2*)src)[i];
    int row = i / (N >> 1), c2 = i % (N >> 1);
    *(__half2*)&dst[(size_t)row * stride + off + 2 * c2] = __floats2half2_rn(v.x, v.y);
}

// ---------------- HMMA GEMM 128x256, 3-stage cp.async, B natural [K][N] -------
#define GP 40
#define BP 264
#define G_AH (128*GP)
#define G_BH (32*BP)
#define G_STAGE_H (G_AH + G_BH)
#define GSTG 3
#define G_SMEM_B (GSTG * G_STAGE_H * 2)   // 81408 bytes
template<typename OutT>
__global__ void __launch_bounds__(256) hgemm_pipe(const __half* __restrict__ A,
                                                  const __half* __restrict__ B,
                                                  OutT* __restrict__ C,
                                                  int M, int N, int K, int ldB) {
    extern __shared__ __half hsm[];
    uint32_t smb = smem_u32(hsm);
    int tid = threadIdx.x;
    int lane = tid & 31, wid = tid >> 5;
    int wm = wid >> 2, wn = wid & 3;
    int m0 = blockIdx.y << 7, n0 = blockIdx.x << 8;

    const int NC = K >> 5;

    auto issue = [&](int c) {
        int s = c % GSTG;
        uint32_t base = smb + s * (G_STAGE_H * 2);
        #pragma unroll
        for (int i = 0; i < 2; i++) {
            int f = tid + i * 256; int r = f >> 2, cc = (f & 3) * 8;
            cp16(base + (r * GP + cc) * 2, A + (size_t)(m0 + r) * K + c * 32 + cc);
        }
        #pragma unroll
        for (int i = 0; i < 4; i++) {
            int f = tid + i * 256; int kr = f >> 5, nc = (f & 31) * 8;
            cp16(base + (G_AH + kr * BP + nc) * 2,
                 B + (size_t)(c * 32 + kr) * ldB + n0 + nc);
        }
        CP_COMMIT();
    };

    issue(0); issue(1);

    float acc[4][8][4];
    #pragma unroll
    for (int i = 0; i < 4; i++)
        #pragma unroll
        for (int j = 0; j < 8; j++)
            #pragma unroll
            for (int k = 0; k < 4; k++) acc[i][j][k] = 0.f;

    int lrow = lane & 15, lhalf = lane >> 4;

    for (int c = 0; c < NC; c++) {
        asm volatile("cp.async.wait_group 1;");
        __syncthreads();
        if (c + 2 < NC) issue(c + 2);

        uint32_t sbase = smb + (c % GSTG) * (G_STAGE_H * 2);
        #pragma unroll
        for (int ks = 0; ks < 2; ks++) {
            uint32_t af[4][4];
            uint32_t bf[8][2];
            #pragma unroll
            for (int mt = 0; mt < 4; mt++) {
                uint32_t ad = sbase + ((wm*64 + mt*16 + lrow) * GP + ks*16 + lhalf*8) * 2;
                ldmatrix_x4(af[mt][0], af[mt][1], af[mt][2], af[mt][3], ad);
            }
            #pragma unroll
            for (int np = 0; np < 4; np++) {
                uint32_t bd = sbase + (G_AH + (ks*16 + lrow) * BP + wn*64 + np*16 + lhalf*8) * 2;
                uint32_t q0, q1, q2, q3;
                ldmatrix_x4_trans(q0, q1, q2, q3, bd);
                bf[np*2+0][0] = q0; bf[np*2+0][1] = q1;
                bf[np*2+1][0] = q2; bf[np*2+1][1] = q3;
            }
            #pragma unroll
            for (int mt = 0; mt < 4; mt++)
                #pragma unroll
                for (int nt = 0; nt < 8; nt++)
                    mma16816(acc[mt][nt], af[mt], bf[nt]);
        }
    }

    int er = lane >> 2, ec = (lane & 3) * 2;
    #pragma unroll
    for (int mt = 0; mt < 4; mt++) {
        int row = m0 + wm*64 + mt*16 + er;
        OutT* Cr0 = C + (size_t)row * N + n0 + wn*64;
        OutT* Cr1 = Cr0 + 8 * N;
        #pragma unroll
        for (int nt = 0; nt < 8; nt++) {
            if constexpr (sizeof(OutT) == 2) {
                *(__half2*)&Cr0[nt*8 + ec] = __floats2half2_rn(acc[mt][nt][0], acc[mt][nt][1]);
                *(__half2*)&Cr1[nt*8 + ec] = __floats2half2_rn(acc[mt][nt][2], acc[mt][nt][3]);
            } else {
                *(float2*)&Cr0[nt*8 + ec] = make_float2(acc[mt][nt][0], acc[mt][nt][1]);
                *(float2*)&Cr1[nt*8 + ec] = make_float2(acc[mt][nt][2], acc[mt][nt][3]);
            }
        }
    }
}

// ---------------- RMSNorm + RoPE (fp16 in) -> fp16 [b][h][t][d] ----------------
// q is additionally pre-scaled by 1/sqrt(H) (rope is linear).
__global__ void normrope_h(const __half* __restrict__ proj, int stride, int coloff,
                           const float* __restrict__ w,
                           const float* __restrict__ cosb,
                           const float* __restrict__ sinb,
                           __half* __restrict__ outh, int NH, float postscale) {
    int gw = (blockIdx.x * blockDim.x + threadIdx.x) >> 5;
    int lane = threadIdx.x & 31;
    if (gw >= Bn * Tn * NH) return;
    int h = gw % NH;
    int bt = gw / NH;
    int t = bt % Tn;
    int b = bt / Tn;

    const __half* p = proj + (size_t)bt * stride + coloff + h * Hn;
    int d0 = lane * 2;
    float2 xa = __half22float2(*(const __half2*)(p + d0));
    float2 xb = __half22float2(*(const __half2*)(p + d0 + 64));
    float ss = xa.x*xa.x + xa.y*xa.y + xb.x*xb.x + xb.y*xb.y;
    #pragma unroll
    for (int o = 16; o; o >>= 1) ss += __shfl_xor_sync(0xffffffffu, ss, o);
    float inv = rsqrtf(ss * (1.0f / 128.0f) + 1e-6f) * postscale;
    float2 wa = *(const float2*)(w + d0);
    float2 wb = *(const float2*)(w + d0 + 64);
    xa.x *= inv * wa.x; xa.y *= inv * wa.y;
    xb.x *= inv * wb.x; xb.y *= inv * wb.y;
    const float* cp = cosb + (size_t)t * Hn;
    const float* sp = sinb + (size_t)t * Hn;
    float2 ca = *(const float2*)(cp + d0), cb = *(const float2*)(cp + d0 + 64);
    float2 sa = *(const float2*)(sp + d0), sb = *(const float2*)(sp + d0 + 64);
    float ya0 = xa.x * ca.x - xb.x * sa.x;
    float ya1 = xa.y * ca.y - xb.y * sa.y;
    float yb0 = xb.x * cb.x + xa.x * sb.x;
    float yb1 = xb.y * cb.y + xa.y * sb.y;
    __half* o = outh + ((size_t)(b * NH + h) * Tn + t) * Hn;
    *(__half2*)(o + d0)      = __floats2half2_rn(ya0, ya1);
    *(__half2*)(o + d0 + 64) = __floats2half2_rn(yb0, yb1);
}

// ---------------- HMMA flash attention (causal, GQA) ---------------------------
// 64 q-rows per CTA, 128 threads, kv tiles of 64, cp.async double buffer,
// descending-q0 order. __launch_bounds__(128,3): cap regs at 170 -> 3 CTAs/SM.
#define AKP 136
#define A_KB (64 * AKP)
#define A_STAGE_H (2 * A_KB)
#define A_SMEM_B (2 * A_STAGE_H * 2)  // 69632 bytes
__global__ void __launch_bounds__(128, 3) attn_mma(const __half* __restrict__ qh,
                                                   const __half* __restrict__ kh,
                                                   const __half* __restrict__ qkvh,
                                                   __half* __restrict__ ctxh) {
    extern __shared__ __half asm_[];
    uint32_t smb = smem_u32(asm_);

    int tid = threadIdx.x, lane = tid & 31, w = tid >> 5;
    int q0 = (gridDim.x - 1 - blockIdx.x) << 6;
    int h = blockIdx.y, b = blockIdx.z;
    int kvh = h >> 2;

    const __half* qb = qh + ((size_t)(b * NQn + h) * Tn + q0) * Hn;
    const __half* kb = kh + (size_t)(b * NKVn + kvh) * Tn * Hn;
    const __half* vb = qkvh + (size_t)b * Tn * NQKV + 2560 + kvh * Hn;

    #pragma unroll
    for (int i = 0; i < 8; i++) {
        int f = tid + i * 128; int r = f >> 4, c8 = (f & 15) << 3;
        *(uint4*)&asm_[r * AKP + c8] = *(const uint4*)(qb + (size_t)r * Hn + c8);
    }
    __syncthreads();
    int lrow = lane & 15, lhalf = lane >> 4;
    uint32_t qf[8][4];
    #pragma unroll
    for (int ks = 0; ks < 8; ks++) {
        uint32_t ad = smb + ((w * 16 + lrow) * AKP + ks * 16 + lhalf * 8) * 2;
        ldmatrix_x4(qf[ks][0], qf[ks][1], qf[ks][2], qf[ks][3], ad);
    }
    __syncthreads();

    auto issue_kv = [&](int jt) {
        uint32_t base = smb + (jt & 1) * (A_STAGE_H * 2);
        int j0 = jt << 6;
        #pragma unroll
        for (int i = 0; i < 8; i++) {
            int f = tid + i * 128; int r = f >> 4, c8 = (f & 15) << 3;
            cp16(base + (r * AKP + c8) * 2, kb + (size_t)(j0 + r) * Hn + c8);
        }
        #pragma unroll
        for (int i = 0; i < 8; i++) {
            int f = tid + i * 128; int r = f >> 4, c8 = (f & 15) << 3;
            cp16(base + (A_KB + r * AKP + c8) * 2, vb + (size_t)(j0 + r) * NQKV + c8);
        }
        CP_COMMIT();
    };

    const int NT = (q0 >> 6) + 1;
    issue_kv(0);

    float oacc[16][4];
    #pragma unroll
    for (int i = 0; i < 16; i++) { oacc[i][0]=0.f; oacc[i][1]=0.f; oacc[i][2]=0.f; oacc[i][3]=0.f; }
    float m0 = -1e30f, m1 = -1e30f, l0 = 0.f, l1 = 0.f;
    int ec = (lane & 3) * 2;
    int r0 = q0 + w * 16 + (lane >> 2);
    int r1 = r0 + 8;

    for (int jt = 0; jt < NT; jt++) {
        int j0 = jt << 6;
        if (jt + 1 < NT) {
            issue_kv(jt + 1);
            asm volatile("cp.async.wait_group 1;");
        } else {
            asm volatile("cp.async.wait_group 0;");
        }
        __syncthreads();
        uint32_t sbase = smb + (jt & 1) * (A_STAGE_H * 2);

        float sacc[8][4];
        #pragma unroll
        for (int i = 0; i < 8; i++) { sacc[i][0]=0.f; sacc[i][1]=0.f; sacc[i][2]=0.f; sacc[i][3]=0.f; }
        #pragma unroll
        for (int ks = 0; ks < 8; ks++) {
            #pragma unroll
            for (int np = 0; np < 4; np++) {
                uint32_t ad = sbase + ((np * 16 + lrow) * AKP + ks * 16 + lhalf * 8) * 2;
                uint32_t t0, t1, t2, t3;
                ldmatrix_x4(t0, t1, t2, t3, ad);
                uint32_t b0[2] = {t0, t2}, b1[2] = {t1, t3};
                mma16816(sacc[np * 2],     qf[ks], b0);
                mma16816(sacc[np * 2 + 1], qf[ks], b1);
            }
        }

        // causal mask (q pre-scaled in normrope)
        #pragma unroll
        for (int nt = 0; nt < 8; nt++) {
            int c = j0 + nt * 8 + ec;
            if (c     > r0) sacc[nt][0] = -1e30f;
            if (c + 1 > r0) sacc[nt][1] = -1e30f;
            if (c     > r1) sacc[nt][2] = -1e30f;
            if (c + 1 > r1) sacc[nt][3] = -1e30f;
        }

        float tm0 = -1e30f, tm1 = -1e30f;
        #pragma unroll
        for (int nt = 0; nt < 8; nt++) {
            tm0 = fmaxf(tm0, fmaxf(sacc[nt][0], sacc[nt][1]));
            tm1 = fmaxf(tm1, fmaxf(sacc[nt][2], sacc[nt][3]));
        }
        tm0 = fmaxf(tm0, __shfl_xor_sync(0xffffffffu, tm0, 1));
        tm0 = fmaxf(tm0, __shfl_xor_sync(0xffffffffu, tm0, 2));
        tm1 = fmaxf(tm1, __shfl_xor_sync(0xffffffffu, tm1, 1));
        tm1 = fmaxf(tm1, __shfl_xor_sync(0xffffffffu, tm1, 2));
        float mn0 = fmaxf(m0, tm0), mn1 = fmaxf(m1, tm1);
        float al0 = __expf(m0 - mn0), al1 = __expf(m1 - mn1);
        m0 = mn0; m1 = mn1;

        float rs0 = 0.f, rs1 = 0.f;
        uint32_t pf[4][4];
        #pragma unroll
        for (int nt = 0; nt < 8; nt++) {
            float p0 = __expf(sacc[nt][0] - mn0);
            float p1 = __expf(sacc[nt][1] - mn0);
            float p2 = __expf(sacc[nt][2] - mn1);
            float p3 = __expf(sacc[nt][3] - mn1);
            rs0 += p0 + p1; rs1 += p2 + p3;
            __half2 v01 = __floats2half2_rn(p0, p1);
            __half2 v23 = __floats2half2_rn(p2, p3);
            int kt = nt >> 1;
            if ((nt & 1) == 0) {
                pf[kt][0] = *(uint32_t*)&v01;
                pf[kt][1] = *(uint32_t*)&v23;
            } else {
                pf[kt][2] = *(uint32_t*)&v01;
                pf[kt][3] = *(uint32_t*)&v23;
            }
        }
        rs0 += __shfl_xor_sync(0xffffffffu, rs0, 1);
        rs0 += __shfl_xor_sync(0xffffffffu, rs0, 2);
        rs1 += __shfl_xor_sync(0xffffffffu, rs1, 1);
        rs1 += __shfl_xor_sync(0xffffffffu, rs1, 2);
        l0 = l0 * al0 + rs0;
        l1 = l1 * al1 + rs1;

        #pragma unroll
        for (int dt = 0; dt < 16; dt++) {
            oacc[dt][0] *= al0; oacc[dt][1] *= al0;
            oacc[dt][2] *= al1; oacc[dt][3] *= al1;
        }

        #pragma unroll
        for (int kt = 0; kt < 4; kt++) {
            #pragma unroll
            for (int np = 0; np < 8; np++) {
                uint32_t ad = sbase + (A_KB + (kt * 16 + lrow) * AKP + np * 16 + lhalf * 8) * 2;
                uint32_t t0, t1, t2, t3;
                ldmatrix_x4_trans(t0, t1, t2, t3, ad);
                uint32_t b0[2] = {t0, t1}, b1[2] = {t2, t3};
                mma16816(oacc[np * 2],     pf[kt], b0);
                mma16816(oacc[np * 2 + 1], pf[kt], b1);
            }
        }
        __syncthreads();
    }

    float inv0 = 1.0f / l0, inv1 = 1.0f / l1;
    __half* o0 = ctxh + (size_t)(b * Tn + r0) * (NQn * Hn) + h * Hn;
    __half* o1 = ctxh + (size_t)(b * Tn + r1) * (NQn * Hn) + h * Hn;
    #pragma unroll
    for (int dt = 0; dt < 16; dt++) {
        __half2 w0 = __floats2half2_rn(oacc[dt][0] * inv0, oacc[dt][1] * inv0);
        __half2 w1 = __floats2half2_rn(oacc[dt][2] * inv1, oacc[dt][3] * inv1);
        *(__half2*)&o0[dt * 8 + ec] = w0;
        *(__half2*)&o1[dt * 8 + ec] = w1;
    }
}

// ---------------- launch ------------------------------------------------------
extern "C" void kernel_launch(void* const* d_in, const int* in_sizes, int n_in,
                              void* d_out, int out_size) {
    (void)in_sizes; (void)n_in; (void)out_size;
    const float* x   = (const float*)d_in[0];
    const float* Wq  = (const float*)d_in[1];
    const float* Wk  = (const float*)d_in[2];
    const float* Wv  = (const float*)d_in[3];
    const float* Wo  = (const float*)d_in[4];
    const float* qnw = (const float*)d_in[5];
    const float* knw = (const float*)d_in[6];
    const float* cosb = (const float*)d_in[7];
    const float* sinb = (const float*)d_in[8];
    float* out = (float*)d_out;

    __half *qkvh, *xh, *wqkvh, *woh, *ctxh, *qh, *kh;
    cudaGetSymbolAddress((void**)&qkvh,  g_qkvh);
    cudaGetSymbolAddress((void**)&xh,    g_xh);
    cudaGetSymbolAddress((void**)&wqkvh, g_wqkvh);
    cudaGetSymbolAddress((void**)&woh,   g_woh);
    cudaGetSymbolAddress((void**)&ctxh,  g_ctxh);
    cudaGetSymbolAddress((void**)&qh,    g_qh);
    cudaGetSymbolAddress((void**)&kh,    g_kh);

    cudaFuncSetAttribute(hgemm_pipe<__half>, cudaFuncAttributeMaxDynamicSharedMemorySize, G_SMEM_B);
    cudaFuncSetAttribute(hgemm_pipe<float>,  cudaFuncAttributeMaxDynamicSharedMemorySize, G_SMEM_B);
    cudaFuncSetAttribute(attn_mma, cudaFuncAttributeMaxDynamicSharedMemorySize, A_SMEM_B);

    // 0) conversions (1 launch for all weights, 1 for x)
    wconv_all<<<20480, 256>>>(Wq, Wk, Wv, Wo, wqkvh, woh);
    f32_to_f16_kernel<<<(BTn * Cn / 4 + 255) / 256, 256>>>(x, xh, BTn * Cn / 4);

    // 1) fused QKV projection -> fp16
    hgemm_pipe<__half><<<dim3(NQKV/256, BTn/128), 256, G_SMEM_B>>>(xh, wqkvh, qkvh, BTn, NQKV, Cn, NQKV);

    // 2) rmsnorm + rope -> fp16 [b][h][t][d]  (q pre-scaled by 1/sqrt(H))
    normrope_h<<<(Bn * Tn * NQn) / 8, 256>>>(qkvh, NQKV, 0,    qnw, cosb, sinb, qh, NQn, SCALE);
    normrope_h<<<(Bn * Tn * NKVn) / 8, 256>>>(qkvh, NQKV, 2048, knw, cosb, sinb, kh, NKVn, 1.0f);

    // 3) causal GQA flash attention (V read in-place from qkvh)
    attn_mma<<<dim3(Tn / 64, NQn, Bn), 128, A_SMEM_B>>>(qh, kh, qkvh, ctxh);

    // 4) output projection -> f32
    hgemm_pipe<float><<<dim3(Cn/256, BTn/128), 256, G_SMEM_B>>>(ctxh, woh, out, BTn, Cn, NQn*Hn, Cn);
}

// round 14
// speedup vs baseline: 1.1445x; 1.0516x over previous
#include <cuda_runtime.h>
#include <cuda_fp16.h>
#include <cstdint>

// Problem constants
#define Bn   2
#define Tn   2048
#define Cn   2048
#define NQn  16
#define NKVn 4
#define Hn   128
#define BTn  (Bn*Tn)        // 4096
#define NQKV 3072           // 2048 q + 512 k + 512 v
#define SCALE 0.08838834764831845f  // 1/sqrt(128)
#define LOG2E 1.4426950408889634f

// ---------------- scratch (device globals) ------------------------------------
__device__ __half g_qkvh[BTn * NQKV];            // fused qkv proj fp16 [bt][3072]
__device__ __half g_xh[BTn * Cn];                // x fp16 [M][K]
__device__ __half g_wqkvh[Cn * NQKV];            // [Wq | Wk | Wv] fp16 [K][3072]
__device__ __half g_woh[(NQn*Hn) * Cn];          // Wo fp16 [K][N]
__device__ __half g_ctxh[BTn * NQn * Hn];        // attention out fp16
__device__ __half g_qh[Bn * NQn * Tn * Hn];      // q fp16 [b][h][t][d] (scaled by SCALE*log2e)
__device__ __half g_kh[Bn * NKVn * Tn * Hn];     // k fp16 [b][kvh][t][d]

// ---------------- helpers ------------------------------------------------------
__device__ __forceinline__ uint32_t smem_u32(const void* p) {
    uint32_t a;
    asm("{ .reg .u64 t; cvta.to.shared.u64 t, %1; cvt.u32.u64 %0, t; }" : "=r"(a) : "l"(p));
    return a;
}
__device__ __forceinline__ void ldmatrix_x4(uint32_t& r0, uint32_t& r1,
                                            uint32_t& r2, uint32_t& r3, uint32_t addr) {
    asm volatile("ldmatrix.sync.aligned.m8n8.x4.shared.b16 {%0,%1,%2,%3}, [%4];"
                 : "=r"(r0), "=r"(r1), "=r"(r2), "=r"(r3) : "r"(addr));
}
__device__ __forceinline__ void ldmatrix_x4_trans(uint32_t& r0, uint32_t& r1,
                                                  uint32_t& r2, uint32_t& r3, uint32_t addr) {
    asm volatile("ldmatrix.sync.aligned.m8n8.x4.trans.shared.b16 {%0,%1,%2,%3}, [%4];"
                 : "=r"(r0), "=r"(r1), "=r"(r2), "=r"(r3) : "r"(addr));
}
__device__ __forceinline__ void ldmatrix_x2_trans(uint32_t& r0, uint32_t& r1, uint32_t addr) {
    asm volatile("ldmatrix.sync.aligned.m8n8.x2.trans.shared.b16 {%0,%1}, [%2];"
                 : "=r"(r0), "=r"(r1) : "r"(addr));
}
__device__ __forceinline__ void mma16816(float* d, const uint32_t* a, const uint32_t* b) {
    asm volatile(
        "mma.sync.aligned.m16n8k16.row.col.f32.f16.f16.f32 "
        "{%0,%1,%2,%3}, {%4,%5,%6,%7}, {%8,%9}, {%0,%1,%2,%3};"
        : "+f"(d[0]), "+f"(d[1]), "+f"(d[2]), "+f"(d[3])
        : "r"(a[0]), "r"(a[1]), "r"(a[2]), "r"(a[3]), "r"(b[0]), "r"(b[1]));
}
__device__ __forceinline__ void cp16(uint32_t dst, const void* src) {
    asm volatile("cp.async.cg.shared.global [%0], [%1], 16;"
                 :: "r"(dst), "l"(__cvta_generic_to_global(src)));
}
#define CP_COMMIT() asm volatile("cp.async.commit_group;")
__device__ __forceinline__ uint32_t ex2_f16x2(uint32_t x) {
    uint32_t r;
    asm volatile("ex2.approx.f16x2 %0, %1;" : "=r"(r) : "r"(x));
    return r;
}
__device__ __forceinline__ float ex2f(float x) {
    float r;
    asm volatile("ex2.approx.f32 %0, %1;" : "=f"(r) : "f"(x));
    return r;
}

// ---------------- fp32 -> fp16 elementwise ------------------------------------
__global__ void f32_to_f16_kernel(const float* __restrict__ in, __half* __restrict__ out, int n4) {
    int i = blockIdx.x * blockDim.x + threadIdx.x;
    if (i < n4) {
        float4 v = ((const float4*)in)[i];
        ((__half2*)out)[2*i]   = __floats2half2_rn(v.x, v.y);
        ((__half2*)out)[2*i+1] = __floats2half2_rn(v.z, v.w);
    }
}

// ---------------- all weight conversions in ONE launch -------------------------
__global__ void wconv_all(const float* __restrict__ Wq, const float* __restrict__ Wk,
                          const float* __restrict__ Wv, const float* __restrict__ Wo,
                          __half* __restrict__ wqkvh, __half* __restrict__ woh) {
    int bid = blockIdx.x, tid = threadIdx.x;
    const float* src; __half* dst; int N, stride, off, i;
    if (bid < 8192)       { src = Wq; dst = wqkvh; N = 2048; stride = NQKV; off = 0;
                            i = bid * 256 + tid; }
    else if (bid < 10240) { src = Wk; dst = wqkvh; N = 512;  stride = NQKV; off = 2048;
                            i = (bid - 8192) * 256 + tid; }
    else if (bid < 12288) { src = Wv; dst = wqkvh; N = 512;  stride = NQKV; off = 2560;
                            i = (bid - 10240) * 256 + tid; }
    else                  { src = Wo; dst = woh;   N = 2048; stride = 2048; off = 0;
                            i = (bid - 12288) * 256 + tid; }
    float2 v = ((const float2*)src)[i];
    int row = i / (N >> 1), c2 = i % (N >> 1);
    *(__half2*)&dst[(size_t)row * stride + off + 2 * c2] = __floats2half2_rn(v.x, v.y);
}

// ---------------- HMMA GEMM 128x256, 3-stage cp.async, B natural [K][N] -------
#define GP 40
#define BP 264
#define G_AH (128*GP)
#define G_BH (32*BP)
#define G_STAGE_H (G_AH + G_BH)
#define GSTG 3
#define G_SMEM_B (GSTG * G_STAGE_H * 2)   // 81408 bytes
template<typename OutT>
__global__ void __launch_bounds__(256) hgemm_pipe(const __half* __restrict__ A,
                                                  const __half* __restrict__ B,
                                                  OutT* __restrict__ C,
                                                  int M, int N, int K, int ldB) {
    extern __shared__ __half hsm[];
    uint32_t smb = smem_u32(hsm);
    int tid = threadIdx.x;
    int lane = tid & 31, wid = tid >> 5;
    int wm = wid >> 2, wn = wid & 3;
    int m0 = blockIdx.y << 7, n0 = blockIdx.x << 8;

    const int NC = K >> 5;

    auto issue = [&](int c) {
        int s = c % GSTG;
        uint32_t base = smb + s * (G_STAGE_H * 2);
        #pragma unroll
        for (int i = 0; i < 2; i++) {
            int f = tid + i * 256; int r = f >> 2, cc = (f & 3) * 8;
            cp16(base + (r * GP + cc) * 2, A + (size_t)(m0 + r) * K + c * 32 + cc);
        }
        #pragma unroll
        for (int i = 0; i < 4; i++) {
            int f = tid + i * 256; int kr = f >> 5, nc = (f & 31) * 8;
            cp16(base + (G_AH + kr * BP + nc) * 2,
                 B + (size_t)(c * 32 + kr) * ldB + n0 + nc);
        }
        CP_COMMIT();
    };

    issue(0); issue(1);

    float acc[4][8][4];
    #pragma unroll
    for (int i = 0; i < 4; i++)
        #pragma unroll
        for (int j = 0; j < 8; j++)
            #pragma unroll
            for (int k = 0; k < 4; k++) acc[i][j][k] = 0.f;

    int lrow = lane & 15, lhalf = lane >> 4;

    for (int c = 0; c < NC; c++) {
        asm volatile("cp.async.wait_group 1;");
        __syncthreads();
        if (c + 2 < NC) issue(c + 2);

        uint32_t sbase = smb + (c % GSTG) * (G_STAGE_H * 2);
        #pragma unroll
        for (int ks = 0; ks < 2; ks++) {
            uint32_t af[4][4];
            uint32_t bf[8][2];
            #pragma unroll
            for (int mt = 0; mt < 4; mt++) {
                uint32_t ad = sbase + ((wm*64 + mt*16 + lrow) * GP + ks*16 + lhalf*8) * 2;
                ldmatrix_x4(af[mt][0], af[mt][1], af[mt][2], af[mt][3], ad);
            }
            #pragma unroll
            for (int np = 0; np < 4; np++) {
                uint32_t bd = sbase + (G_AH + (ks*16 + lrow) * BP + wn*64 + np*16 + lhalf*8) * 2;
                uint32_t q0, q1, q2, q3;
                ldmatrix_x4_trans(q0, q1, q2, q3, bd);
                bf[np*2+0][0] = q0; bf[np*2+0][1] = q1;
                bf[np*2+1][0] = q2; bf[np*2+1][1] = q3;
            }
            #pragma unroll
            for (int mt = 0; mt < 4; mt++)
                #pragma unroll
                for (int nt = 0; nt < 8; nt++)
                    mma16816(acc[mt][nt], af[mt], bf[nt]);
        }
    }

    int er = lane >> 2, ec = (lane & 3) * 2;
    #pragma unroll
    for (int mt = 0; mt < 4; mt++) {
        int row = m0 + wm*64 + mt*16 + er;
        OutT* Cr0 = C + (size_t)row * N + n0 + wn*64;
        OutT* Cr1 = Cr0 + 8 * N;
        #pragma unroll
        for (int nt = 0; nt < 8; nt++) {
            if constexpr (sizeof(OutT) == 2) {
                *(__half2*)&Cr0[nt*8 + ec] = __floats2half2_rn(acc[mt][nt][0], acc[mt][nt][1]);
                *(__half2*)&Cr1[nt*8 + ec] = __floats2half2_rn(acc[mt][nt][2], acc[mt][nt][3]);
            } else {
                *(float2*)&Cr0[nt*8 + ec] = make_float2(acc[mt][nt][0], acc[mt][nt][1]);
                *(float2*)&Cr1[nt*8 + ec] = make_float2(acc[mt][nt][2], acc[mt][nt][3]);
            }
        }
    }
}

// ---------------- RMSNorm + RoPE (fp16 in) -> fp16 [b][h][t][d] ----------------
__global__ void normrope_h(const __half* __restrict__ proj, int stride, int coloff,
                           const float* __restrict__ w,
                           const float* __restrict__ cosb,
                           const float* __restrict__ sinb,
                           __half* __restrict__ outh, int NH, float postscale) {
    int gw = (blockIdx.x * blockDim.x + threadIdx.x) >> 5;
    int lane = threadIdx.x & 31;
    if (gw >= Bn * Tn * NH) return;
    int h = gw % NH;
    int bt = gw / NH;
    int t = bt % Tn;
    int b = bt / Tn;

    const __half* p = proj + (size_t)bt * stride + coloff + h * Hn;
    int d0 = lane * 2;
    float2 xa = __half22float2(*(const __half2*)(p + d0));
    float2 xb = __half22float2(*(const __half2*)(p + d0 + 64));
    float ss = xa.x*xa.x + xa.y*xa.y + xb.x*xb.x + xb.y*xb.y;
    #pragma unroll
    for (int o = 16; o; o >>= 1) ss += __shfl_xor_sync(0xffffffffu, ss, o);
    float inv = rsqrtf(ss * (1.0f / 128.0f) + 1e-6f) * postscale;
    float2 wa = *(const float2*)(w + d0);
    float2 wb = *(const float2*)(w + d0 + 64);
    xa.x *= inv * wa.x; xa.y *= inv * wa.y;
    xb.x *= inv * wb.x; xb.y *= inv * wb.y;
    const float* cp = cosb + (size_t)t * Hn;
    const float* sp = sinb + (size_t)t * Hn;
    float2 ca = *(const float2*)(cp + d0), cb = *(const float2*)(cp + d0 + 64);
    float2 sa = *(const float2*)(sp + d0), sb = *(const float2*)(sp + d0 + 64);
    float ya0 = xa.x * ca.x - xb.x * sa.x;
    float ya1 = xa.y * ca.y - xb.y * sa.y;
    float yb0 = xb.x * cb.x + xa.x * sb.x;
    float yb1 = xb.y * cb.y + xa.y * sb.y;
    __half* o = outh + ((size_t)(b * NH + h) * Tn + t) * Hn;
    *(__half2*)(o + d0)      = __floats2half2_rn(ya0, ya1);
    *(__half2*)(o + d0 + 64) = __floats2half2_rn(yb0, yb1);
}

// ---------------- HMMA flash attention (causal, GQA) ---------------------------
// 64 q-rows/CTA, 128 threads, kv tiles of 64, cp.async double buffer, descending
// order, 3 CTAs/SM. Softmax in log2 domain via ex2.approx.f16x2; row-sum l via a
// ones-column MMA (V smem pitch slack cols 128-135); mask only on last tile.
#define AKP 136
#define A_KB (64 * AKP)
#define A_STAGE_H (2 * A_KB)
#define A_SMEM_B (2 * A_STAGE_H * 2)  // 69632 bytes
__global__ void __launch_bounds__(128, 3) attn_mma(const __half* __restrict__ qh,
                                                   const __half* __restrict__ kh,
                                                   const __half* __restrict__ qkvh,
                                                   __half* __restrict__ ctxh) {
    extern __shared__ __half asm_[];
    uint32_t smb = smem_u32(asm_);

    int tid = threadIdx.x, lane = tid & 31, w = tid >> 5;
    int q0 = (gridDim.x - 1 - blockIdx.x) << 6;
    int h = blockIdx.y, b = blockIdx.z;
    int kvh = h >> 2;

    const __half* qb = qh + ((size_t)(b * NQn + h) * Tn + q0) * Hn;
    const __half* kb = kh + (size_t)(b * NKVn + kvh) * Tn * Hn;
    const __half* vb = qkvh + (size_t)b * Tn * NQKV + 2560 + kvh * Hn;

    #pragma unroll
    for (int i = 0; i < 8; i++) {
        int f = tid + i * 128; int r = f >> 4, c8 = (f & 15) << 3;
        *(uint4*)&asm_[r * AKP + c8] = *(const uint4*)(qb + (size_t)r * Hn + c8);
    }
    __syncthreads();
    int lrow = lane & 15, lhalf = lane >> 4;
    uint32_t qf[8][4];
    #pragma unroll
    for (int ks = 0; ks < 8; ks++) {
        uint32_t ad = smb + ((w * 16 + lrow) * AKP + ks * 16 + lhalf * 8) * 2;
        ldmatrix_x4(qf[ks][0], qf[ks][1], qf[ks][2], qf[ks][3], ad);
    }
    __syncthreads();

    // init ones-column region (V tile cols 128-135) for both stages:
    // col 128 = 1.0h, cols 129-135 = 0. 128 threads x (stage, row).
    {
        int st = tid >> 6, r = tid & 63;
        uint32_t base = smb + st * (A_STAGE_H * 2) + (A_KB + r * AKP + 128) * 2;
        uint4 ones = make_uint4(0x00003C00u, 0u, 0u, 0u);
        *(uint4*)(asm_ + (base - smb) / 2) = ones;   // same address arithmetic in generic space
    }

    auto issue_kv = [&](int jt) {
        uint32_t base = smb + (jt & 1) * (A_STAGE_H * 2);
        int j0 = jt << 6;
        #pragma unroll
        for (int i = 0; i < 8; i++) {
            int f = tid + i * 128; int r = f >> 4, c8 = (f & 15) << 3;
            cp16(base + (r * AKP + c8) * 2, kb + (size_t)(j0 + r) * Hn + c8);
        }
        #pragma unroll
        for (int i = 0; i < 8; i++) {
            int f = tid + i * 128; int r = f >> 4, c8 = (f & 15) << 3;
            cp16(base + (A_KB + r * AKP + c8) * 2, vb + (size_t)(j0 + r) * NQKV + c8);
        }
        CP_COMMIT();
    };

    const int NT = (q0 >> 6) + 1;
    issue_kv(0);

    float oacc[16][4];
    #pragma unroll
    for (int i = 0; i < 16; i++) { oacc[i][0]=0.f; oacc[i][1]=0.f; oacc[i][2]=0.f; oacc[i][3]=0.f; }
    float lacc[4] = {0.f, 0.f, 0.f, 0.f};
    float m0 = -1e30f, m1 = -1e30f;
    int ec = (lane & 3) * 2;
    int r0 = q0 + w * 16 + (lane >> 2);
    int r1 = r0 + 8;

    for (int jt = 0; jt < NT; jt++) {
        int j0 = jt << 6;
        if (jt + 1 < NT) {
            issue_kv(jt + 1);
            asm volatile("cp.async.wait_group 1;");
        } else {
            asm volatile("cp.async.wait_group 0;");
        }
        __syncthreads();
        uint32_t sbase = smb + (jt & 1) * (A_STAGE_H * 2);

        float sacc[8][4];
        #pragma unroll
        for (int i = 0; i < 8; i++) { sacc[i][0]=0.f; sacc[i][1]=0.f; sacc[i][2]=0.f; sacc[i][3]=0.f; }
        #pragma unroll
        for (int ks = 0; ks < 8; ks++) {
            #pragma unroll
            for (int np = 0; np < 4; np++) {
                uint32_t ad = sbase + ((np * 16 + lrow) * AKP + ks * 16 + lhalf * 8) * 2;
                uint32_t t0, t1, t2, t3;
                ldmatrix_x4(t0, t1, t2, t3, ad);
                uint32_t b0[2] = {t0, t2}, b1[2] = {t1, t3};
                mma16816(sacc[np * 2],     qf[ks], b0);
                mma16816(sacc[np * 2 + 1], qf[ks], b1);
            }
        }

        // causal mask — provably only needed on the last tile (j0 == q0)
        if (jt == NT - 1) {
            #pragma unroll
            for (int nt = 0; nt < 8; nt++) {
                int c = j0 + nt * 8 + ec;
                if (c     > r0) sacc[nt][0] = -1e30f;
                if (c + 1 > r0) sacc[nt][1] = -1e30f;
                if (c     > r1) sacc[nt][2] = -1e30f;
                if (c + 1 > r1) sacc[nt][3] = -1e30f;
            }
        }

        float tm0 = -1e30f, tm1 = -1e30f;
        #pragma unroll
        for (int nt = 0; nt < 8; nt++) {
            tm0 = fmaxf(tm0, fmaxf(sacc[nt][0], sacc[nt][1]));
            tm1 = fmaxf(tm1, fmaxf(sacc[nt][2], sacc[nt][3]));
        }
        tm0 = fmaxf(tm0, __shfl_xor_sync(0xffffffffu, tm0, 1));
        tm0 = fmaxf(tm0, __shfl_xor_sync(0xffffffffu, tm0, 2));
        tm1 = fmaxf(tm1, __shfl_xor_sync(0xffffffffu, tm1, 1));
        tm1 = fmaxf(tm1, __shfl_xor_sync(0xffffffffu, tm1, 2));
        float mn0 = fmaxf(m0, tm0), mn1 = fmaxf(m1, tm1);
        float al0 = ex2f(m0 - mn0), al1 = ex2f(m1 - mn1);
        m0 = mn0; m1 = mn1;

        // p = exp2(s - mn) via dual fp16 ex2, straight into fragments
        uint32_t pf[4][4];
        #pragma unroll
        for (int nt = 0; nt < 8; nt++) {
            __half2 d01 = __floats2half2_rn(sacc[nt][0] - mn0, sacc[nt][1] - mn0);
            __half2 d23 = __floats2half2_rn(sacc[nt][2] - mn1, sacc[nt][3] - mn1);
            uint32_t p01 = ex2_f16x2(*(uint32_t*)&d01);
            uint32_t p23 = ex2_f16x2(*(uint32_t*)&d23);
            int kt = nt >> 1;
            if ((nt & 1) == 0) { pf[kt][0] = p01; pf[kt][1] = p23; }
            else               { pf[kt][2] = p01; pf[kt][3] = p23; }
        }

        #pragma unroll
        for (int dt = 0; dt < 16; dt++) {
            oacc[dt][0] *= al0; oacc[dt][1] *= al0;
            oacc[dt][2] *= al1; oacc[dt][3] *= al1;
        }
        lacc[0] *= al0; lacc[1] *= al0; lacc[2] *= al1; lacc[3] *= al1;

        #pragma unroll
        for (int kt = 0; kt < 4; kt++) {
            #pragma unroll
            for (int np = 0; np < 8; np++) {
                uint32_t ad = sbase + (A_KB + (kt * 16 + lrow) * AKP + np * 16 + lhalf * 8) * 2;
                uint32_t t0, t1, t2, t3;
                ldmatrix_x4_trans(t0, t1, t2, t3, ad);
                uint32_t b0[2] = {t0, t1}, b1[2] = {t2, t3};
                mma16816(oacc[np * 2],     pf[kt], b0);
                mma16816(oacc[np * 2 + 1], pf[kt], b1);
            }
            // ones-column: accumulate row sums into lacc
            uint32_t w0, w1;
            ldmatrix_x2_trans(w0, w1, sbase + (A_KB + (kt * 16 + lrow) * AKP + 128) * 2);
            uint32_t ob[2] = {w0, w1};
            mma16816(lacc, pf[kt], ob);
        }
        __syncthreads();
    }

    // l lives in quad-lane 0's lacc[0]/lacc[2] (column 128 of each row)
    float l0 = __shfl_sync(0xffffffffu, lacc[0], lane & ~3);
    float l1 = __shfl_sync(0xffffffffu, lacc[2], lane & ~3);
    float inv0 = 1.0f / l0, inv1 = 1.0f / l1;
    __half* o0 = ctxh + (size_t)(b * Tn + r0) * (NQn * Hn) + h * Hn;
    __half* o1 = ctxh + (size_t)(b * Tn + r1) * (NQn * Hn) + h * Hn;
    #pragma unroll
    for (int dt = 0; dt < 16; dt++) {
        __half2 w0 = __floats2half2_rn(oacc[dt][0] * inv0, oacc[dt][1] * inv0);
        __half2 w1 = __floats2half2_rn(oacc[dt][2] * inv1, oacc[dt][3] * inv1);
        *(__half2*)&o0[dt * 8 + ec] = w0;
        *(__half2*)&o1[dt * 8 + ec] = w1;
    }
}

// ---------------- launch ------------------------------------------------------
extern "C" void kernel_launch(void* const* d_in, const int* in_sizes, int n_in,
                              void* d_out, int out_size) {
    (void)in_sizes; (void)n_in; (void)out_size;
    const float* x   = (const float*)d_in[0];
    const float* Wq  = (const float*)d_in[1];
    const float* Wk  = (const float*)d_in[2];
    const float* Wv  = (const float*)d_in[3];
    const float* Wo  = (const float*)d_in[4];
    const float* qnw = (const float*)d_in[5];
    const float* knw = (const float*)d_in[6];
    const float* cosb = (const float*)d_in[7];
    const float* sinb = (const float*)d_in[8];
    float* out = (float*)d_out;

    __half *qkvh, *xh, *wqkvh, *woh, *ctxh, *qh, *kh;
    cudaGetSymbolAddress((void**)&qkvh,  g_qkvh);
    cudaGetSymbolAddress((void**)&xh,    g_xh);
    cudaGetSymbolAddress((void**)&wqkvh, g_wqkvh);
    cudaGetSymbolAddress((void**)&woh,   g_woh);
    cudaGetSymbolAddress((void**)&ctxh,  g_ctxh);
    cudaGetSymbolAddress((void**)&qh,    g_qh);
    cudaGetSymbolAddress((void**)&kh,    g_kh);

    cudaFuncSetAttribute(hgemm_pipe<__half>, cudaFuncAttributeMaxDynamicSharedMemorySize, G_SMEM_B);
    cudaFuncSetAttribute(hgemm_pipe<float>,  cudaFuncAttributeMaxDynamicSharedMemorySize, G_SMEM_B);
    cudaFuncSetAttribute(attn_mma, cudaFuncAttributeMaxDynamicSharedMemorySize, A_SMEM_B);

    // 0) conversions (1 launch for all weights, 1 for x)
    wconv_all<<<20480, 256>>>(Wq, Wk, Wv, Wo, wqkvh, woh);
    f32_to_f16_kernel<<<(BTn * Cn / 4 + 255) / 256, 256>>>(x, xh, BTn * Cn / 4);

    // 1) fused QKV projection -> fp16
    hgemm_pipe<__half><<<dim3(NQKV/256, BTn/128), 256, G_SMEM_B>>>(xh, wqkvh, qkvh, BTn, NQKV, Cn, NQKV);

    // 2) rmsnorm + rope -> fp16 [b][h][t][d]  (q pre-scaled by SCALE*log2e)
    normrope_h<<<(Bn * Tn * NQn) / 8, 256>>>(qkvh, NQKV, 0,    qnw, cosb, sinb, qh, NQn, SCALE * LOG2E);
    normrope_h<<<(Bn * Tn * NKVn) / 8, 256>>>(qkvh, NQKV, 2048, knw, cosb, sinb, kh, NKVn, 1.0f);

    // 3) causal GQA flash attention (V read in-place from qkvh)
    attn_mma<<<dim3(Tn / 64, NQn, Bn), 128, A_SMEM_B>>>(qh, kh, qkvh, ctxh);

    // 4) output projection -> f32
    hgemm_pipe<float><<<dim3(Cn/256, BTn/128), 256, G_SMEM_B>>>(ctxh, woh, out, BTn, Cn, NQn*Hn, Cn);
}

// round 16
// speedup vs baseline: 1.1627x; 1.0159x over previous
#include <cuda_runtime.h>
#include <cuda_fp16.h>
#include <cstdint>

// Problem constants
#define Bn   2
#define Tn   2048
#define Cn   2048
#define NQn  16
#define NKVn 4
#define Hn   128
#define BTn  (Bn*Tn)        // 4096
#define NQKV 3072           // 2048 q + 512 k + 512 v
#define SCALE 0.08838834764831845f  // 1/sqrt(128)
#define LOG2E 1.4426950408889634f

// ---------------- scratch (device globals) ------------------------------------
__device__ __half g_qkvh[BTn * NQKV];            // fused qkv proj fp16 [bt][3072]
__device__ __half g_xh[BTn * Cn];                // x fp16 [M][K]
__device__ __half g_wqkvh[Cn * NQKV];            // [Wq | Wk | Wv] fp16 [K][3072]
__device__ __half g_woh[(NQn*Hn) * Cn];          // Wo fp16 [K][N]
__device__ __half g_ctxh[BTn * NQn * Hn];        // attention out fp16
__device__ __half g_qh[Bn * NQn * Tn * Hn];      // q fp16 [b][h][t][d] (scaled SCALE*log2e)
__device__ __half g_kh[Bn * NKVn * Tn * Hn];     // k fp16 [b][kvh][t][d]

// ---------------- helpers ------------------------------------------------------
__device__ __forceinline__ uint32_t smem_u32(const void* p) {
    uint32_t a;
    asm("{ .reg .u64 t; cvta.to.shared.u64 t, %1; cvt.u32.u64 %0, t; }" : "=r"(a) : "l"(p));
    return a;
}
__device__ __forceinline__ void ldmatrix_x4(uint32_t& r0, uint32_t& r1,
                                            uint32_t& r2, uint32_t& r3, uint32_t addr) {
    asm volatile("ldmatrix.sync.aligned.m8n8.x4.shared.b16 {%0,%1,%2,%3}, [%4];"
                 : "=r"(r0), "=r"(r1), "=r"(r2), "=r"(r3) : "r"(addr));
}
__device__ __forceinline__ void ldmatrix_x4_trans(uint32_t& r0, uint32_t& r1,
                                                  uint32_t& r2, uint32_t& r3, uint32_t addr) {
    asm volatile("ldmatrix.sync.aligned.m8n8.x4.trans.shared.b16 {%0,%1,%2,%3}, [%4];"
                 : "=r"(r0), "=r"(r1), "=r"(r2), "=r"(r3) : "r"(addr));
}
__device__ __forceinline__ void ldmatrix_x2_trans(uint32_t& r0, uint32_t& r1, uint32_t addr) {
    asm volatile("ldmatrix.sync.aligned.m8n8.x2.trans.shared.b16 {%0,%1}, [%2];"
                 : "=r"(r0), "=r"(r1) : "r"(addr));
}
__device__ __forceinline__ void mma16816(float* d, const uint32_t* a, const uint32_t* b) {
    asm volatile(
        "mma.sync.aligned.m16n8k16.row.col.f32.f16.f16.f32 "
        "{%0,%1,%2,%3}, {%4,%5,%6,%7}, {%8,%9}, {%0,%1,%2,%3};"
        : "+f"(d[0]), "+f"(d[1]), "+f"(d[2]), "+f"(d[3])
        : "r"(a[0]), "r"(a[1]), "r"(a[2]), "r"(a[3]), "r"(b[0]), "r"(b[1]));
}
__device__ __forceinline__ void cp16(uint32_t dst, const void* src) {
    asm volatile("cp.async.cg.shared.global [%0], [%1], 16;"
                 :: "r"(dst), "l"(__cvta_generic_to_global(src)));
}
#define CP_COMMIT() asm volatile("cp.async.commit_group;")
__device__ __forceinline__ uint32_t ex2_f16x2(uint32_t x) {
    uint32_t r;
    asm volatile("ex2.approx.f16x2 %0, %1;" : "=r"(r) : "r"(x));
    return r;
}
__device__ __forceinline__ float ex2f(float x) {
    float r;
    asm volatile("ex2.approx.f32 %0, %1;" : "=f"(r) : "f"(x));
    return r;
}

// ---------------- all conversions (weights + x) in ONE launch ------------------
__global__ void conv_all(const float* __restrict__ Wq, const float* __restrict__ Wk,
                         const float* __restrict__ Wv, const float* __restrict__ Wo,
                         const float* __restrict__ x,
                         __half* __restrict__ wqkvh, __half* __restrict__ woh,
                         __half* __restrict__ xh) {
    int bid = blockIdx.x, tid = threadIdx.x;
    if (bid >= 20480) {
        int i = (bid - 20480) * 256 + tid;
        float2 v = ((const float2*)x)[i];
        ((__half2*)xh)[i] = __floats2half2_rn(v.x, v.y);
        return;
    }
    const float* src; __half* dst; int N, stride, off, i;
    if (bid < 8192)       { src = Wq; dst = wqkvh; N = 2048; stride = NQKV; off = 0;
                            i = bid * 256 + tid; }
    else if (bid < 10240) { src = Wk; dst = wqkvh; N = 512;  stride = NQKV; off = 2048;
                            i = (bid - 8192) * 256 + tid; }
    else if (bid < 12288) { src = Wv; dst = wqkvh; N = 512;  stride = NQKV; off = 2560;
                            i = (bid - 10240) * 256 + tid; }
    else                  { src = Wo; dst = woh;   N = 2048; stride = 2048; off = 0;
                            i = (bid - 12288) * 256 + tid; }
    float2 v = ((const float2*)src)[i];
    int row = i / (N >> 1), c2 = i % (N >> 1);
    *(__half2*)&dst[(size_t)row * stride + off + 2 * c2] = __floats2half2_rn(v.x, v.y);
}

// ---------------- HMMA GEMM 128x128, 3-stage cp.async, 2 CTAs/SM --------------
// C[M,N] = A[M,K]f16 @ B[K,N]f16 (natural layouts); warp grid 2m x 4n,
// warp tile 64x32; B fragments via trans ldmatrix.
#define GP 40
#define BP2 136                           // B tile pitch (128 cols + pad)
#define G_AH (128*GP)                     // 5120 halfs
#define G_BH (32*BP2)                     // 4352 halfs
#define G_STAGE_H (G_AH + G_BH)           // 9472 halfs
#define GSTG 3
#define G_SMEM_B (GSTG * G_STAGE_H * 2)   // 56832 bytes
template<typename OutT>
__global__ void __launch_bounds__(256, 2) hgemm_pipe(const __half* __restrict__ A,
                                                     const __half* __restrict__ B,
                                                     OutT* __restrict__ C,
                                                     int M, int N, int K, int ldB) {
    extern __shared__ __half hsm[];
    uint32_t smb = smem_u32(hsm);
    int tid = threadIdx.x;
    int lane = tid & 31, wid = tid >> 5;
    int wm = wid >> 2, wn = wid & 3;          // 2m x 4n, warp tile 64x32
    int m0 = blockIdx.y << 7, n0 = blockIdx.x << 7;

    const int NC = K >> 5;

    auto issue = [&](int c) {
        int s = c % GSTG;
        uint32_t base = smb + s * (G_STAGE_H * 2);
        // A: 128 rows x 32 halfs = 512 x 16B -> 2 per thread
        #pragma unroll
        for (int i = 0; i < 2; i++) {
            int f = tid + i * 256; int r = f >> 2, cc = (f & 3) * 8;
            cp16(base + (r * GP + cc) * 2, A + (size_t)(m0 + r) * K + c * 32 + cc);
        }
        // B: 32 k-rows x 128 halfs = 512 x 16B -> 2 per thread
        #pragma unroll
        for (int i = 0; i < 2; i++) {
            int f = tid + i * 256; int kr = f >> 4, nc = (f & 15) * 8;
            cp16(base + (G_AH + kr * BP2 + nc) * 2,
                 B + (size_t)(c * 32 + kr) * ldB + n0 + nc);
        }
        CP_COMMIT();
    };

    issue(0); issue(1);

    float acc[4][4][4];
    #pragma unroll
    for (int i = 0; i < 4; i++)
        #pragma unroll
        for (int j = 0; j < 4; j++)
            #pragma unroll
            for (int k = 0; k < 4; k++) acc[i][j][k] = 0.f;

    int lrow = lane & 15, lhalf = lane >> 4;

    for (int c = 0; c < NC; c++) {
        asm volatile("cp.async.wait_group 1;");
        __syncthreads();
        if (c + 2 < NC) issue(c + 2);

        uint32_t sbase = smb + (c % GSTG) * (G_STAGE_H * 2);
        #pragma unroll
        for (int ks = 0; ks < 2; ks++) {
            uint32_t af[4][4];
            uint32_t bf[4][2];
            #pragma unroll
            for (int mt = 0; mt < 4; mt++) {
                uint32_t ad = sbase + ((wm*64 + mt*16 + lrow) * GP + ks*16 + lhalf*8) * 2;
                ldmatrix_x4(af[mt][0], af[mt][1], af[mt][2], af[mt][3], ad);
            }
            #pragma unroll
            for (int np = 0; np < 2; np++) {
                uint32_t bd = sbase + (G_AH + (ks*16 + lrow) * BP2 + wn*32 + np*16 + lhalf*8) * 2;
                uint32_t q0, q1, q2, q3;
                ldmatrix_x4_trans(q0, q1, q2, q3, bd);
                bf[np*2+0][0] = q0; bf[np*2+0][1] = q1;
                bf[np*2+1][0] = q2; bf[np*2+1][1] = q3;
            }
            #pragma unroll
            for (int mt = 0; mt < 4; mt++)
                #pragma unroll
                for (int nt = 0; nt < 4; nt++)
                    mma16816(acc[mt][nt], af[mt], bf[nt]);
        }
    }

    int er = lane >> 2, ec = (lane & 3) * 2;
    #pragma unroll
    for (int mt = 0; mt < 4; mt++) {
        int row = m0 + wm*64 + mt*16 + er;
        OutT* Cr0 = C + (size_t)row * N + n0 + wn*32;
        OutT* Cr1 = Cr0 + 8 * N;
        #pragma unroll
        for (int nt = 0; nt < 4; nt++) {
            if constexpr (sizeof(OutT) == 2) {
                *(__half2*)&Cr0[nt*8 + ec] = __floats2half2_rn(acc[mt][nt][0], acc[mt][nt][1]);
                *(__half2*)&Cr1[nt*8 + ec] = __floats2half2_rn(acc[mt][nt][2], acc[mt][nt][3]);
            } else {
                *(float2*)&Cr0[nt*8 + ec] = make_float2(acc[mt][nt][0], acc[mt][nt][1]);
                *(float2*)&Cr1[nt*8 + ec] = make_float2(acc[mt][nt][2], acc[mt][nt][3]);
            }
        }
    }
}

// ---------------- RMSNorm + RoPE (fp16 in) -> fp16 [b][h][t][d] ----------------
__global__ void normrope_h(const __half* __restrict__ proj, int stride, int coloff,
                           const float* __restrict__ w,
                           const float* __restrict__ cosb,
                           const float* __restrict__ sinb,
                           __half* __restrict__ outh, int NH, float postscale) {
    int gw = (blockIdx.x * blockDim.x + threadIdx.x) >> 5;
    int lane = threadIdx.x & 31;
    if (gw >= Bn * Tn * NH) return;
    int h = gw % NH;
    int bt = gw / NH;
    int t = bt % Tn;
    int b = bt / Tn;

    const __half* p = proj + (size_t)bt * stride + coloff + h * Hn;
    int d0 = lane * 2;
    float2 xa = __half22float2(*(const __half2*)(p + d0));
    float2 xb = __half22float2(*(const __half2*)(p + d0 + 64));
    float ss = xa.x*xa.x + xa.y*xa.y + xb.x*xb.x + xb.y*xb.y;
    #pragma unroll
    for (int o = 16; o; o >>= 1) ss += __shfl_xor_sync(0xffffffffu, ss, o);
    float inv = rsqrtf(ss * (1.0f / 128.0f) + 1e-6f) * postscale;
    float2 wa = *(const float2*)(w + d0);
    float2 wb = *(const float2*)(w + d0 + 64);
    xa.x *= inv * wa.x; xa.y *= inv * wa.y;
    xb.x *= inv * wb.x; xb.y *= inv * wb.y;
    const float* cp = cosb + (size_t)t * Hn;
    const float* sp = sinb + (size_t)t * Hn;
    float2 ca = *(const float2*)(cp + d0), cb = *(const float2*)(cp + d0 + 64);
    float2 sa = *(const float2*)(sp + d0), sb = *(const float2*)(sp + d0 + 64);
    float ya0 = xa.x * ca.x - xb.x * sa.x;
    float ya1 = xa.y * ca.y - xb.y * sa.y;
    float yb0 = xb.x * cb.x + xa.x * sb.x;
    float yb1 = xb.y * cb.y + xa.y * sb.y;
    __half* o = outh + ((size_t)(b * NH + h) * Tn + t) * Hn;
    *(__half2*)(o + d0)      = __floats2half2_rn(ya0, ya1);
    *(__half2*)(o + d0 + 64) = __floats2half2_rn(yb0, yb1);
}

// ---------------- HMMA flash attention (causal, GQA) ---------------------------
// 64 q-rows/CTA, 128 threads, kv tiles of 64, cp.async double buffer, descending
// order, 3 CTAs/SM, ex2.f16x2 softmax, ones-column row-sum, last-tile-only mask.
#define AKP 136
#define A_KB (64 * AKP)
#define A_STAGE_H (2 * A_KB)
#define A_SMEM_B (2 * A_STAGE_H * 2)  // 69632 bytes
__global__ void __launch_bounds__(128, 3) attn_mma(const __half* __restrict__ qh,
                                                   const __half* __restrict__ kh,
                                                   const __half* __restrict__ qkvh,
                                                   __half* __restrict__ ctxh) {
    extern __shared__ __half asm_[];
    uint32_t smb = smem_u32(asm_);

    int tid = threadIdx.x, lane = tid & 31, w = tid >> 5;
    int q0 = (gridDim.x - 1 - blockIdx.x) << 6;
    int h = blockIdx.y, b = blockIdx.z;
    int kvh = h >> 2;

    const __half* qb = qh + ((size_t)(b * NQn + h) * Tn + q0) * Hn;
    const __half* kb = kh + (size_t)(b * NKVn + kvh) * Tn * Hn;
    const __half* vb = qkvh + (size_t)b * Tn * NQKV + 2560 + kvh * Hn;

    #pragma unroll
    for (int i = 0; i < 8; i++) {
        int f = tid + i * 128; int r = f >> 4, c8 = (f & 15) << 3;
        *(uint4*)&asm_[r * AKP + c8] = *(const uint4*)(qb + (size_t)r * Hn + c8);
    }
    __syncthreads();
    int lrow = lane & 15, lhalf = lane >> 4;
    uint32_t qf[8][4];
    #pragma unroll
    for (int ks = 0; ks < 8; ks++) {
        uint32_t ad = smb + ((w * 16 + lrow) * AKP + ks * 16 + lhalf * 8) * 2;
        ldmatrix_x4(qf[ks][0], qf[ks][1], qf[ks][2], qf[ks][3], ad);
    }
    __syncthreads();

    // ones-column region (V tile cols 128-135) for both stages
    {
        int st = tid >> 6, r = tid & 63;
        uint32_t base = smb + st * (A_STAGE_H * 2) + (A_KB + r * AKP + 128) * 2;
        uint4 ones = make_uint4(0x00003C00u, 0u, 0u, 0u);
        *(uint4*)(asm_ + (base - smb) / 2) = ones;
    }

    auto issue_kv = [&](int jt) {
        uint32_t base = smb + (jt & 1) * (A_STAGE_H * 2);
        int j0 = jt << 6;
        #pragma unroll
        for (int i = 0; i < 8; i++) {
            int f = tid + i * 128; int r = f >> 4, c8 = (f & 15) << 3;
            cp16(base + (r * AKP + c8) * 2, kb + (size_t)(j0 + r) * Hn + c8);
        }
        #pragma unroll
        for (int i = 0; i < 8; i++) {
            int f = tid + i * 128; int r = f >> 4, c8 = (f & 15) << 3;
            cp16(base + (A_KB + r * AKP + c8) * 2, vb + (size_t)(j0 + r) * NQKV + c8);
        }
        CP_COMMIT();
    };

    const int NT = (q0 >> 6) + 1;
    issue_kv(0);

    float oacc[16][4];
    #pragma unroll
    for (int i = 0; i < 16; i++) { oacc[i][0]=0.f; oacc[i][1]=0.f; oacc[i][2]=0.f; oacc[i][3]=0.f; }
    float lacc[4] = {0.f, 0.f, 0.f, 0.f};
    float m0 = -1e30f, m1 = -1e30f;
    int ec = (lane & 3) * 2;
    int r0 = q0 + w * 16 + (lane >> 2);
    int r1 = r0 + 8;

    for (int jt = 0; jt < NT; jt++) {
        int j0 = jt << 6;
        if (jt + 1 < NT) {
            issue_kv(jt + 1);
            asm volatile("cp.async.wait_group 1;");
        } else {
            asm volatile("cp.async.wait_group 0;");
        }
        __syncthreads();
        uint32_t sbase = smb + (jt & 1) * (A_STAGE_H * 2);

        float sacc[8][4];
        #pragma unroll
        for (int i = 0; i < 8; i++) { sacc[i][0]=0.f; sacc[i][1]=0.f; sacc[i][2]=0.f; sacc[i][3]=0.f; }
        #pragma unroll
        for (int ks = 0; ks < 8; ks++) {
            #pragma unroll
            for (int np = 0; np < 4; np++) {
                uint32_t ad = sbase + ((np * 16 + lrow) * AKP + ks * 16 + lhalf * 8) * 2;
                uint32_t t0, t1, t2, t3;
                ldmatrix_x4(t0, t1, t2, t3, ad);
                uint32_t b0[2] = {t0, t2}, b1[2] = {t1, t3};
                mma16816(sacc[np * 2],     qf[ks], b0);
                mma16816(sacc[np * 2 + 1], qf[ks], b1);
            }
        }

        if (jt == NT - 1) {
            #pragma unroll
            for (int nt = 0; nt < 8; nt++) {
                int c = j0 + nt * 8 + ec;
                if (c     > r0) sacc[nt][0] = -1e30f;
                if (c + 1 > r0) sacc[nt][1] = -1e30f;
                if (c     > r1) sacc[nt][2] = -1e30f;
                if (c + 1 > r1) sacc[nt][3] = -1e30f;
            }
        }

        float tm0 = -1e30f, tm1 = -1e30f;
        #pragma unroll
        for (int nt = 0; nt < 8; nt++) {
            tm0 = fmaxf(tm0, fmaxf(sacc[nt][0], sacc[nt][1]));
            tm1 = fmaxf(tm1, fmaxf(sacc[nt][2], sacc[nt][3]));
        }
        tm0 = fmaxf(tm0, __shfl_xor_sync(0xffffffffu, tm0, 1));
        tm0 = fmaxf(tm0, __shfl_xor_sync(0xffffffffu, tm0, 2));
        tm1 = fmaxf(tm1, __shfl_xor_sync(0xffffffffu, tm1, 1));
        tm1 = fmaxf(tm1, __shfl_xor_sync(0xffffffffu, tm1, 2));
        float mn0 = fmaxf(m0, tm0), mn1 = fmaxf(m1, tm1);
        float al0 = ex2f(m0 - mn0), al1 = ex2f(m1 - mn1);
        m0 = mn0; m1 = mn1;

        uint32_t pf[4][4];
        #pragma unroll
        for (int nt = 0; nt < 8; nt++) {
            __half2 d01 = __floats2half2_rn(sacc[nt][0] - mn0, sacc[nt][1] - mn0);
            __half2 d23 = __floats2half2_rn(sacc[nt][2] - mn1, sacc[nt][3] - mn1);
            uint32_t p01 = ex2_f16x2(*(uint32_t*)&d01);
            uint32_t p23 = ex2_f16x2(*(uint32_t*)&d23);
            int kt = nt >> 1;
            if ((nt & 1) == 0) { pf[kt][0] = p01; pf[kt][1] = p23; }
            else               { pf[kt][2] = p01; pf[kt][3] = p23; }
        }

        #pragma unroll
        for (int dt = 0; dt < 16; dt++) {
            oacc[dt][0] *= al0; oacc[dt][1] *= al0;
            oacc[dt][2] *= al1; oacc[dt][3] *= al1;
        }
        lacc[0] *= al0; lacc[1] *= al0; lacc[2] *= al1; lacc[3] *= al1;

        #pragma unroll
        for (int kt = 0; kt < 4; kt++) {
            #pragma unroll
            for (int np = 0; np < 8; np++) {
                uint32_t ad = sbase + (A_KB + (kt * 16 + lrow) * AKP + np * 16 + lhalf * 8) * 2;
                uint32_t t0, t1, t2, t3;
                ldmatrix_x4_trans(t0, t1, t2, t3, ad);
                uint32_t b0[2] = {t0, t1}, b1[2] = {t2, t3};
                mma16816(oacc[np * 2],     pf[kt], b0);
                mma16816(oacc[np * 2 + 1], pf[kt], b1);
            }
            uint32_t w0, w1;
            ldmatrix_x2_trans(w0, w1, sbase + (A_KB + (kt * 16 + lrow) * AKP + 128) * 2);
            uint32_t ob[2] = {w0, w1};
            mma16816(lacc, pf[kt], ob);
        }
        __syncthreads();
    }

    float l0 = __shfl_sync(0xffffffffu, lacc[0], lane & ~3);
    float l1 = __shfl_sync(0xffffffffu, lacc[2], lane & ~3);
    float inv0 = 1.0f / l0, inv1 = 1.0f / l1;
    __half* o0 = ctxh + (size_t)(b * Tn + r0) * (NQn * Hn) + h * Hn;
    __half* o1 = ctxh + (size_t)(b * Tn + r1) * (NQn * Hn) + h * Hn;
    #pragma unroll
    for (int dt = 0; dt < 16; dt++) {
        __half2 w0 = __floats2half2_rn(oacc[dt][0] * inv0, oacc[dt][1] * inv0);
        __half2 w1 = __floats2half2_rn(oacc[dt][2] * inv1, oacc[dt][3] * inv1);
        *(__half2*)&o0[dt * 8 + ec] = w0;
        *(__half2*)&o1[dt * 8 + ec] = w1;
    }
}

// ---------------- launch ------------------------------------------------------
extern "C" void kernel_launch(void* const* d_in, const int* in_sizes, int n_in,
                              void* d_out, int out_size) {
    (void)in_sizes; (void)n_in; (void)out_size;
    const float* x   = (const float*)d_in[0];
    const float* Wq  = (const float*)d_in[1];
    const float* Wk  = (const float*)d_in[2];
    const float* Wv  = (const float*)d_in[3];
    const float* Wo  = (const float*)d_in[4];
    const float* qnw = (const float*)d_in[5];
    const float* knw = (const float*)d_in[6];
    const float* cosb = (const float*)d_in[7];
    const float* sinb = (const float*)d_in[8];
    float* out = (float*)d_out;

    __half *qkvh, *xh, *wqkvh, *woh, *ctxh, *qh, *kh;
    cudaGetSymbolAddress((void**)&qkvh,  g_qkvh);
    cudaGetSymbolAddress((void**)&xh,    g_xh);
    cudaGetSymbolAddress((void**)&wqkvh, g_wqkvh);
    cudaGetSymbolAddress((void**)&woh,   g_woh);
    cudaGetSymbolAddress((void**)&ctxh,  g_ctxh);
    cudaGetSymbolAddress((void**)&qh,    g_qh);
    cudaGetSymbolAddress((void**)&kh,    g_kh);

    cudaFuncSetAttribute(hgemm_pipe<__half>, cudaFuncAttributeMaxDynamicSharedMemorySize, G_SMEM_B);
    cudaFuncSetAttribute(hgemm_pipe<float>,  cudaFuncAttributeMaxDynamicSharedMemorySize, G_SMEM_B);
    cudaFuncSetAttribute(attn_mma, cudaFuncAttributeMaxDynamicSharedMemorySize, A_SMEM_B);

    // 0) all conversions in one launch
    conv_all<<<36864, 256>>>(Wq, Wk, Wv, Wo, x, wqkvh, woh, xh);

    // 1) fused QKV projection -> fp16 (128x128 tiles, 2 CTAs/SM)
    hgemm_pipe<__half><<<dim3(NQKV/128, BTn/128), 256, G_SMEM_B>>>(xh, wqkvh, qkvh, BTn, NQKV, Cn, NQKV);

    // 2) rmsnorm + rope -> fp16 [b][h][t][d]  (q pre-scaled by SCALE*log2e)
    normrope_h<<<(Bn * Tn * NQn) / 8, 256>>>(qkvh, NQKV, 0,    qnw, cosb, sinb, qh, NQn, SCALE * LOG2E);
    normrope_h<<<(Bn * Tn * NKVn) / 8, 256>>>(qkvh, NQKV, 2048, knw, cosb, sinb, kh, NKVn, 1.0f);

    // 3) causal GQA flash attention (V read in-place from qkvh)
    attn_mma<<<dim3(Tn / 64, NQn, Bn), 128, A_SMEM_B>>>(qh, kh, qkvh, ctxh);

    // 4) output projection -> f32
    hgemm_pipe<float><<<dim3(Cn/128, BTn/128), 256, G_SMEM_B>>>(ctxh, woh, out, BTn, Cn, NQn*Hn, Cn);
}

// round 17
// speedup vs baseline: 1.2473x; 1.0727x over previous
#include <cuda_runtime.h>
#include <cuda_fp16.h>
#include <cstdint>

// Problem constants
#define Bn   2
#define Tn   2048
#define Cn   2048
#define NQn  16
#define NKVn 4
#define Hn   128
#define BTn  (Bn*Tn)        // 4096
#define NQKV 3072           // 2048 q + 512 k + 512 v
#define SCALE 0.08838834764831845f  // 1/sqrt(128)
#define LOG2E 1.4426950408889634f

// ---------------- scratch (device globals) ------------------------------------
__device__ __half g_qkvh[BTn * NQKV];            // fused qkv proj fp16 [bt][3072]
__device__ __half g_xh[BTn * Cn];                // x fp16 [M][K]
__device__ __half g_wqkvh[Cn * NQKV];            // [Wq | Wk | Wv] fp16 [K][3072]
__device__ __half g_woh[(NQn*Hn) * Cn];          // Wo fp16 [K][N]
__device__ __half g_ctxh[BTn * NQn * Hn];        // attention out fp16
__device__ __half g_qh[Bn * NQn * Tn * Hn];      // q fp16 [b][h][t][d] (scaled SCALE*log2e)
__device__ __half g_kh[Bn * NKVn * Tn * Hn];     // k fp16 [b][kvh][t][d]

// ---------------- helpers ------------------------------------------------------
__device__ __forceinline__ uint32_t smem_u32(const void* p) {
    uint32_t a;
    asm("{ .reg .u64 t; cvta.to.shared.u64 t, %1; cvt.u32.u64 %0, t; }" : "=r"(a) : "l"(p));
    return a;
}
__device__ __forceinline__ void ldmatrix_x4(uint32_t& r0, uint32_t& r1,
                                            uint32_t& r2, uint32_t& r3, uint32_t addr) {
    asm volatile("ldmatrix.sync.aligned.m8n8.x4.shared.b16 {%0,%1,%2,%3}, [%4];"
                 : "=r"(r0), "=r"(r1), "=r"(r2), "=r"(r3) : "r"(addr));
}
__device__ __forceinline__ void ldmatrix_x4_trans(uint32_t& r0, uint32_t& r1,
                                                  uint32_t& r2, uint32_t& r3, uint32_t addr) {
    asm volatile("ldmatrix.sync.aligned.m8n8.x4.trans.shared.b16 {%0,%1,%2,%3}, [%4];"
                 : "=r"(r0), "=r"(r1), "=r"(r2), "=r"(r3) : "r"(addr));
}
__device__ __forceinline__ void ldmatrix_x2_trans(uint32_t& r0, uint32_t& r1, uint32_t addr) {
    asm volatile("ldmatrix.sync.aligned.m8n8.x2.trans.shared.b16 {%0,%1}, [%2];"
                 : "=r"(r0), "=r"(r1) : "r"(addr));
}
__device__ __forceinline__ void mma16816(float* d, const uint32_t* a, const uint32_t* b) {
    asm volatile(
        "mma.sync.aligned.m16n8k16.row.col.f32.f16.f16.f32 "
        "{%0,%1,%2,%3}, {%4,%5,%6,%7}, {%8,%9}, {%0,%1,%2,%3};"
        : "+f"(d[0]), "+f"(d[1]), "+f"(d[2]), "+f"(d[3])
        : "r"(a[0]), "r"(a[1]), "r"(a[2]), "r"(a[3]), "r"(b[0]), "r"(b[1]));
}
__device__ __forceinline__ void cp16(uint32_t dst, const void* src) {
    asm volatile("cp.async.cg.shared.global [%0], [%1], 16;"
                 :: "r"(dst), "l"(__cvta_generic_to_global(src)));
}
#define CP_COMMIT() asm volatile("cp.async.commit_group;")
__device__ __forceinline__ uint32_t ex2_f16x2(uint32_t x) {
    uint32_t r;
    asm volatile("ex2.approx.f16x2 %0, %1;" : "=r"(r) : "r"(x));
    return r;
}
__device__ __forceinline__ float ex2f(float x) {
    float r;
    asm volatile("ex2.approx.f32 %0, %1;" : "=f"(r) : "f"(x));
    return r;
}

// ---------------- all conversions (weights + x), float4/thread -----------------
// regions over float4 elements (256-thread blocks):
//   [0,4096)      Wq -> wqkvh stride 3072 off 0      (2048x2048)
//   [4096,5120)   Wk -> wqkvh stride 3072 off 2048   (2048x512)
//   [5120,6144)   Wv -> wqkvh stride 3072 off 2560   (2048x512)
//   [6144,10240)  Wo -> woh   stride 2048 off 0      (2048x2048)
//   [10240,18432) x  -> xh    contiguous
__global__ void conv_all(const float* __restrict__ Wq, const float* __restrict__ Wk,
                         const float* __restrict__ Wv, const float* __restrict__ Wo,
                         const float* __restrict__ x,
                         __half* __restrict__ wqkvh, __half* __restrict__ woh,
                         __half* __restrict__ xh) {
    int bid = blockIdx.x, tid = threadIdx.x;
    if (bid >= 10240) {
        int i = (bid - 10240) * 256 + tid;
        float4 v = ((const float4*)x)[i];
        ((__half2*)xh)[2*i]   = __floats2half2_rn(v.x, v.y);
        ((__half2*)xh)[2*i+1] = __floats2half2_rn(v.z, v.w);
        return;
    }
    const float* src; __half* dst; int N4, stride, off, i;
    if (bid < 4096)      { src = Wq; dst = wqkvh; N4 = 512; stride = NQKV; off = 0;
                           i = bid * 256 + tid; }
    else if (bid < 5120) { src = Wk; dst = wqkvh; N4 = 128; stride = NQKV; off = 2048;
                           i = (bid - 4096) * 256 + tid; }
    else if (bid < 6144) { src = Wv; dst = wqkvh; N4 = 128; stride = NQKV; off = 2560;
                           i = (bid - 5120) * 256 + tid; }
    else                 { src = Wo; dst = woh;   N4 = 512; stride = 2048; off = 0;
                           i = (bid - 6144) * 256 + tid; }
    float4 v = ((const float4*)src)[i];
    int row = i / N4, c4 = i % N4;
    __half* d = &dst[(size_t)row * stride + off + 4 * c4];
    *(__half2*)d       = __floats2half2_rn(v.x, v.y);
    *(__half2*)(d + 2) = __floats2half2_rn(v.z, v.w);
}

// ---------------- HMMA GEMM 128x128, 4-stage cp.async, 2 CTAs/SM --------------
#define GP 40
#define BP2 136
#define G_AH (128*GP)                     // 5120 halfs
#define G_BH (32*BP2)                     // 4352 halfs
#define G_STAGE_H (G_AH + G_BH)           // 9472 halfs
#define GSTG 4
#define G_SMEM_B (GSTG * G_STAGE_H * 2)   // 75776 bytes
template<typename OutT>
__global__ void __launch_bounds__(256, 2) hgemm_pipe(const __half* __restrict__ A,
                                                     const __half* __restrict__ B,
                                                     OutT* __restrict__ C,
                                                     int M, int N, int K, int ldB) {
    extern __shared__ __half hsm[];
    uint32_t smb = smem_u32(hsm);
    int tid = threadIdx.x;
    int lane = tid & 31, wid = tid >> 5;
    int wm = wid >> 2, wn = wid & 3;          // 2m x 4n, warp tile 64x32
    int m0 = blockIdx.y << 7, n0 = blockIdx.x << 7;

    const int NC = K >> 5;

    auto issue = [&](int c) {
        int s = c & (GSTG - 1);
        uint32_t base = smb + s * (G_STAGE_H * 2);
        #pragma unroll
        for (int i = 0; i < 2; i++) {
            int f = tid + i * 256; int r = f >> 2, cc = (f & 3) * 8;
            cp16(base + (r * GP + cc) * 2, A + (size_t)(m0 + r) * K + c * 32 + cc);
        }
        #pragma unroll
        for (int i = 0; i < 2; i++) {
            int f = tid + i * 256; int kr = f >> 4, nc = (f & 15) * 8;
            cp16(base + (G_AH + kr * BP2 + nc) * 2,
                 B + (size_t)(c * 32 + kr) * ldB + n0 + nc);
        }
        CP_COMMIT();
    };

    issue(0); issue(1); issue(2);

    float acc[4][4][4];
    #pragma unroll
    for (int i = 0; i < 4; i++)
        #pragma unroll
        for (int j = 0; j < 4; j++)
            #pragma unroll
            for (int k = 0; k < 4; k++) acc[i][j][k] = 0.f;

    int lrow = lane & 15, lhalf = lane >> 4;

    for (int c = 0; c < NC; c++) {
        asm volatile("cp.async.wait_group 2;");
        __syncthreads();
        if (c + 3 < NC) issue(c + 3);

        uint32_t sbase = smb + (c & (GSTG - 1)) * (G_STAGE_H * 2);
        #pragma unroll
        for (int ks = 0; ks < 2; ks++) {
            uint32_t af[4][4];
            uint32_t bf[4][2];
            #pragma unroll
            for (int mt = 0; mt < 4; mt++) {
                uint32_t ad = sbase + ((wm*64 + mt*16 + lrow) * GP + ks*16 + lhalf*8) * 2;
                ldmatrix_x4(af[mt][0], af[mt][1], af[mt][2], af[mt][3], ad);
            }
            #pragma unroll
            for (int np = 0; np < 2; np++) {
                uint32_t bd = sbase + (G_AH + (ks*16 + lrow) * BP2 + wn*32 + np*16 + lhalf*8) * 2;
                uint32_t q0, q1, q2, q3;
                ldmatrix_x4_trans(q0, q1, q2, q3, bd);
                bf[np*2+0][0] = q0; bf[np*2+0][1] = q1;
                bf[np*2+1][0] = q2; bf[np*2+1][1] = q3;
            }
            #pragma unroll
            for (int mt = 0; mt < 4; mt++)
                #pragma unroll
                for (int nt = 0; nt < 4; nt++)
                    mma16816(acc[mt][nt], af[mt], bf[nt]);
        }
    }

    int er = lane >> 2, ec = (lane & 3) * 2;
    #pragma unroll
    for (int mt = 0; mt < 4; mt++) {
        int row = m0 + wm*64 + mt*16 + er;
        OutT* Cr0 = C + (size_t)row * N + n0 + wn*32;
        OutT* Cr1 = Cr0 + 8 * N;
        #pragma unroll
        for (int nt = 0; nt < 4; nt++) {
            if constexpr (sizeof(OutT) == 2) {
                *(__half2*)&Cr0[nt*8 + ec] = __floats2half2_rn(acc[mt][nt][0], acc[mt][nt][1]);
                *(__half2*)&Cr1[nt*8 + ec] = __floats2half2_rn(acc[mt][nt][2], acc[mt][nt][3]);
            } else {
                *(float2*)&Cr0[nt*8 + ec] = make_float2(acc[mt][nt][0], acc[mt][nt][1]);
                *(float2*)&Cr1[nt*8 + ec] = make_float2(acc[mt][nt][2], acc[mt][nt][3]);
            }
        }
    }
}

// ---------------- RMSNorm + RoPE (merged q+k, one launch) ----------------------
// blocks [0, 8192): q rows (NH=16, off 0, scale SCALE*LOG2E) -> qh
// blocks [8192, 10240): k rows (NH=4, off 2048, scale 1)     -> kh
__global__ void normrope_all(const __half* __restrict__ proj,
                             const float* __restrict__ qnw,
                             const float* __restrict__ knw,
                             const float* __restrict__ cosb,
                             const float* __restrict__ sinb,
                             __half* __restrict__ qh,
                             __half* __restrict__ kh) {
    int bid = blockIdx.x;
    bool isQ = (bid < 8192);
    int NH      = isQ ? NQn : NKVn;
    int coloff  = isQ ? 0 : 2048;
    float pscale = isQ ? (SCALE * LOG2E) : 1.0f;
    const float* w = isQ ? qnw : knw;
    __half* outh = isQ ? qh : kh;
    int lbid = isQ ? bid : (bid - 8192);

    int gw = (lbid * 256 + (int)threadIdx.x) >> 5;
    int lane = threadIdx.x & 31;
    int h = gw % NH;
    int bt = gw / NH;
    int t = bt % Tn;
    int b = bt / Tn;

    const __half* p = proj + (size_t)bt * NQKV + coloff + h * Hn;
    int d0 = lane * 2;
    float2 xa = __half22float2(*(const __half2*)(p + d0));
    float2 xb = __half22float2(*(const __half2*)(p + d0 + 64));
    float ss = xa.x*xa.x + xa.y*xa.y + xb.x*xb.x + xb.y*xb.y;
    #pragma unroll
    for (int o = 16; o; o >>= 1) ss += __shfl_xor_sync(0xffffffffu, ss, o);
    float inv = rsqrtf(ss * (1.0f / 128.0f) + 1e-6f) * pscale;
    float2 wa = *(const float2*)(w + d0);
    float2 wb = *(const float2*)(w + d0 + 64);
    xa.x *= inv * wa.x; xa.y *= inv * wa.y;
    xb.x *= inv * wb.x; xb.y *= inv * wb.y;
    const float* cp = cosb + (size_t)t * Hn;
    const float* sp = sinb + (size_t)t * Hn;
    float2 ca = *(const float2*)(cp + d0), cb = *(const float2*)(cp + d0 + 64);
    float2 sa = *(const float2*)(sp + d0), sb = *(const float2*)(sp + d0 + 64);
    float ya0 = xa.x * ca.x - xb.x * sa.x;
    float ya1 = xa.y * ca.y - xb.y * sa.y;
    float yb0 = xb.x * cb.x + xa.x * sb.x;
    float yb1 = xb.y * cb.y + xa.y * sb.y;
    __half* o = outh + ((size_t)(b * NH + h) * Tn + t) * Hn;
    *(__half2*)(o + d0)      = __floats2half2_rn(ya0, ya1);
    *(__half2*)(o + d0 + 64) = __floats2half2_rn(yb0, yb1);
}

// ---------------- HMMA flash attention (causal, GQA) ---------------------------
// 64 q-rows/CTA, 128 threads, kv tiles of 64, cp.async double buffer, descending
// order, 3 CTAs/SM, ex2.f16x2 softmax, ones-column row-sum, last-tile-only mask.
#define AKP 136
#define A_KB (64 * AKP)
#define A_STAGE_H (2 * A_KB)
#define A_SMEM_B (2 * A_STAGE_H * 2)  // 69632 bytes
__global__ void __launch_bounds__(128, 3) attn_mma(const __half* __restrict__ qh,
                                                   const __half* __restrict__ kh,
                                                   const __half* __restrict__ qkvh,
                                                   __half* __restrict__ ctxh) {
    extern __shared__ __half asm_[];
    uint32_t smb = smem_u32(asm_);

    int tid = threadIdx.x, lane = tid & 31, w = tid >> 5;
    int q0 = (gridDim.x - 1 - blockIdx.x) << 6;
    int h = blockIdx.y, b = blockIdx.z;
    int kvh = h >> 2;

    const __half* qb = qh + ((size_t)(b * NQn + h) * Tn + q0) * Hn;
    const __half* kb = kh + (size_t)(b * NKVn + kvh) * Tn * Hn;
    const __half* vb = qkvh + (size_t)b * Tn * NQKV + 2560 + kvh * Hn;

    #pragma unroll
    for (int i = 0; i < 8; i++) {
        int f = tid + i * 128; int r = f >> 4, c8 = (f & 15) << 3;
        *(uint4*)&asm_[r * AKP + c8] = *(const uint4*)(qb + (size_t)r * Hn + c8);
    }
    __syncthreads();
    int lrow = lane & 15, lhalf = lane >> 4;
    uint32_t qf[8][4];
    #pragma unroll
    for (int ks = 0; ks < 8; ks++) {
        uint32_t ad = smb + ((w * 16 + lrow) * AKP + ks * 16 + lhalf * 8) * 2;
        ldmatrix_x4(qf[ks][0], qf[ks][1], qf[ks][2], qf[ks][3], ad);
    }
    __syncthreads();

    // ones-column region (V tile cols 128-135) for both stages
    {
        int st = tid >> 6, r = tid & 63;
        uint32_t base = smb + st * (A_STAGE_H * 2) + (A_KB + r * AKP + 128) * 2;
        uint4 ones = make_uint4(0x00003C00u, 0u, 0u, 0u);
        *(uint4*)(asm_ + (base - smb) / 2) = ones;
    }

    auto issue_kv = [&](int jt) {
        uint32_t base = smb + (jt & 1) * (A_STAGE_H * 2);
        int j0 = jt << 6;
        #pragma unroll
        for (int i = 0; i < 8; i++) {
            int f = tid + i * 128; int r = f >> 4, c8 = (f & 15) << 3;
            cp16(base + (r * AKP + c8) * 2, kb + (size_t)(j0 + r) * Hn + c8);
        }
        #pragma unroll
        for (int i = 0; i < 8; i++) {
            int f = tid + i * 128; int r = f >> 4, c8 = (f & 15) << 3;
            cp16(base + (A_KB + r * AKP + c8) * 2, vb + (size_t)(j0 + r) * NQKV + c8);
        }
        CP_COMMIT();
    };

    const int NT = (q0 >> 6) + 1;
    issue_kv(0);

    float oacc[16][4];
    #pragma unroll
    for (int i = 0; i < 16; i++) { oacc[i][0]=0.f; oacc[i][1]=0.f; oacc[i][2]=0.f; oacc[i][3]=0.f; }
    float lacc[4] = {0.f, 0.f, 0.f, 0.f};
    float m0 = -1e30f, m1 = -1e30f;
    int ec = (lane & 3) * 2;
    int r0 = q0 + w * 16 + (lane >> 2);
    int r1 = r0 + 8;

    for (int jt = 0; jt < NT; jt++) {
        int j0 = jt << 6;
        if (jt + 1 < NT) {
            issue_kv(jt + 1);
            asm volatile("cp.async.wait_group 1;");
        } else {
            asm volatile("cp.async.wait_group 0;");
        }
        __syncthreads();
        uint32_t sbase = smb + (jt & 1) * (A_STAGE_H * 2);

        float sacc[8][4];
        #pragma unroll
        for (int i = 0; i < 8; i++) { sacc[i][0]=0.f; sacc[i][1]=0.f; sacc[i][2]=0.f; sacc[i][3]=0.f; }
        #pragma unroll
        for (int ks = 0; ks < 8; ks++) {
            #pragma unroll
            for (int np = 0; np < 4; np++) {
                uint32_t ad = sbase + ((np * 16 + lrow) * AKP + ks * 16 + lhalf * 8) * 2;
                uint32_t t0, t1, t2, t3;
                ldmatrix_x4(t0, t1, t2, t3, ad);
                uint32_t b0[2] = {t0, t2}, b1[2] = {t1, t3};
                mma16816(sacc[np * 2],     qf[ks], b0);
                mma16816(sacc[np * 2 + 1], qf[ks], b1);
            }
        }

        if (jt == NT - 1) {
            #pragma unroll
            for (int nt = 0; nt < 8; nt++) {
                int c = j0 + nt * 8 + ec;
                if (c     > r0) sacc[nt][0] = -1e30f;
                if (c + 1 > r0) sacc[nt][1] = -1e30f;
                if (c     > r1) sacc[nt][2] = -1e30f;
                if (c + 1 > r1) sacc[nt][3] = -1e30f;
            }
        }

        float tm0 = -1e30f, tm1 = -1e30f;
        #pragma unroll
        for (int nt = 0; nt < 8; nt++) {
            tm0 = fmaxf(tm0, fmaxf(sacc[nt][0], sacc[nt][1]));
            tm1 = fmaxf(tm1, fmaxf(sacc[nt][2], sacc[nt][3]));
        }
        tm0 = fmaxf(tm0, __shfl_xor_sync(0xffffffffu, tm0, 1));
        tm0 = fmaxf(tm0, __shfl_xor_sync(0xffffffffu, tm0, 2));
        tm1 = fmaxf(tm1, __shfl_xor_sync(0xffffffffu, tm1, 1));
        tm1 = fmaxf(tm1, __shfl_xor_sync(0xffffffffu, tm1, 2));
        float mn0 = fmaxf(m0, tm0), mn1 = fmaxf(m1, tm1);
        float al0 = ex2f(m0 - mn0), al1 = ex2f(m1 - mn1);
        m0 = mn0; m1 = mn1;

        uint32_t pf[4][4];
        #pragma unroll
        for (int nt = 0; nt < 8; nt++) {
            __half2 d01 = __floats2half2_rn(sacc[nt][0] - mn0, sacc[nt][1] - mn0);
            __half2 d23 = __floats2half2_rn(sacc[nt][2] - mn1, sacc[nt][3] - mn1);
            uint32_t p01 = ex2_f16x2(*(uint32_t*)&d01);
            uint32_t p23 = ex2_f16x2(*(uint32_t*)&d23);
            int kt = nt >> 1;
            if ((nt & 1) == 0) { pf[kt][0] = p01; pf[kt][1] = p23; }
            else               { pf[kt][2] = p01; pf[kt][3] = p23; }
        }

        #pragma unroll
        for (int dt = 0; dt < 16; dt++) {
            oacc[dt][0] *= al0; oacc[dt][1] *= al0;
            oacc[dt][2] *= al1; oacc[dt][3] *= al1;
        }
        lacc[0] *= al0; lacc[1] *= al0; lacc[2] *= al1; lacc[3] *= al1;

        #pragma unroll
        for (int kt = 0; kt < 4; kt++) {
            #pragma unroll
            for (int np = 0; np < 8; np++) {
                uint32_t ad = sbase + (A_KB + (kt * 16 + lrow) * AKP + np * 16 + lhalf * 8) * 2;
                uint32_t t0, t1, t2, t3;
                ldmatrix_x4_trans(t0, t1, t2, t3, ad);
                uint32_t b0[2] = {t0, t1}, b1[2] = {t2, t3};
                mma16816(oacc[np * 2],     pf[kt], b0);
                mma16816(oacc[np * 2 + 1], pf[kt], b1);
            }
            uint32_t w0, w1;
            ldmatrix_x2_trans(w0, w1, sbase + (A_KB + (kt * 16 + lrow) * AKP + 128) * 2);
            uint32_t ob[2] = {w0, w1};
            mma16816(lacc, pf[kt], ob);
        }
        __syncthreads();
    }

    float l0 = __shfl_sync(0xffffffffu, lacc[0], lane & ~3);
    float l1 = __shfl_sync(0xffffffffu, lacc[2], lane & ~3);
    float inv0 = 1.0f / l0, inv1 = 1.0f / l1;
    __half* o0 = ctxh + (size_t)(b * Tn + r0) * (NQn * Hn) + h * Hn;
    __half* o1 = ctxh + (size_t)(b * Tn + r1) * (NQn * Hn) + h * Hn;
    #pragma unroll
    for (int dt = 0; dt < 16; dt++) {
        __half2 w0 = __floats2half2_rn(oacc[dt][0] * inv0, oacc[dt][1] * inv0);
        __half2 w1 = __floats2half2_rn(oacc[dt][2] * inv1, oacc[dt][3] * inv1);
        *(__half2*)&o0[dt * 8 + ec] = w0;
        *(__half2*)&o1[dt * 8 + ec] = w1;
    }
}

// ---------------- launch ------------------------------------------------------
extern "C" void kernel_launch(void* const* d_in, const int* in_sizes, int n_in,
                              void* d_out, int out_size) {
    (void)in_sizes; (void)n_in; (void)out_size;
    const float* x   = (const float*)d_in[0];
    const float* Wq  = (const float*)d_in[1];
    const float* Wk  = (const float*)d_in[2];
    const float* Wv  = (const float*)d_in[3];
    const float* Wo  = (const float*)d_in[4];
    const float* qnw = (const float*)d_in[5];
    const float* knw = (const float*)d_in[6];
    const float* cosb = (const float*)d_in[7];
    const float* sinb = (const float*)d_in[8];
    float* out = (float*)d_out;

    __half *qkvh, *xh, *wqkvh, *woh, *ctxh, *qh, *kh;
    cudaGetSymbolAddress((void**)&qkvh,  g_qkvh);
    cudaGetSymbolAddress((void**)&xh,    g_xh);
    cudaGetSymbolAddress((void**)&wqkvh, g_wqkvh);
    cudaGetSymbolAddress((void**)&woh,   g_woh);
    cudaGetSymbolAddress((void**)&ctxh,  g_ctxh);
    cudaGetSymbolAddress((void**)&qh,    g_qh);
    cudaGetSymbolAddress((void**)&kh,    g_kh);

    cudaFuncSetAttribute(hgemm_pipe<__half>, cudaFuncAttributeMaxDynamicSharedMemorySize, G_SMEM_B);
    cudaFuncSetAttribute(hgemm_pipe<float>,  cudaFuncAttributeMaxDynamicSharedMemorySize, G_SMEM_B);
    cudaFuncSetAttribute(attn_mma, cudaFuncAttributeMaxDynamicSharedMemorySize, A_SMEM_B);

    // 0) all conversions in one launch (float4 per thread)
    conv_all<<<18432, 256>>>(Wq, Wk, Wv, Wo, x, wqkvh, woh, xh);

    // 1) fused QKV projection -> fp16 (128x128 tiles, 4-stage, 2 CTAs/SM)
    hgemm_pipe<__half><<<dim3(NQKV/128, BTn/128), 256, G_SMEM_B>>>(xh, wqkvh, qkvh, BTn, NQKV, Cn, NQKV);

    // 2) rmsnorm + rope, q+k in one launch
    normrope_all<<<10240, 256>>>(qkvh, qnw, knw, cosb, sinb, qh, kh);

    // 3) causal GQA flash attention (V read in-place from qkvh)
    attn_mma<<<dim3(Tn / 64, NQn, Bn), 128, A_SMEM_B>>>(qh, kh, qkvh, ctxh);

    // 4) output projection -> f32
    hgemm_pipe<float><<<dim3(Cn/128, BTn/128), 256, G_SMEM_B>>>(ctxh, woh, out, BTn, Cn, NQn*Hn, Cn);
}